// round 5
// baseline (speedup 1.0000x reference)
#include <cuda_runtime.h>

#define NN   4096
#define DIM  256
#define NE   131072

// ---------------- scratch (device globals: no allocation allowed) ----------
__device__ float g_T0[NN * DIM];   // relu(x @ W_high)
__device__ float g_T1[NN * DIM];   // d_inv @ T0
__device__ float g_T2[NN * DIM];   // lap @ T1
__device__ float g_Hh[NN * DIM];   // d_inv @ T2
__device__ float g_XW[NN * DIM];   // x @ W_conv
__device__ float g_Hl[NN * DIM];   // scatter accumulator
__device__ int   g_deg[NN];
__device__ float g_dis[NN];        // deg^{-1/2}
__device__ int   g_is64;           // edge_index dtype flag

// ---------------- generic N=256 SGEMM: C[M,256] = A[M,K] @ B[K,256] --------
// Tile 128x64, BK=16, 256 threads, 8x4 micro-tile per thread.
template <int DO_RELU>
__global__ __launch_bounds__(256, 2)
void gemm_n256(const float* __restrict__ A, const float* __restrict__ B,
               float* __restrict__ C, int K)
{
    constexpr int BM = 128, BN = 64, BK = 16, TM = 8, TN = 4, N = 256;
    __shared__ float As[BK][BM];   // k-major (transposed) for conflict-free reads
    __shared__ float Bs[BK][BN];

    const int tid  = threadIdx.x;
    const int brow = blockIdx.y * BM;
    const int bcol = blockIdx.x * BN;
    const int ty   = tid >> 4;            // 0..15 -> rows ty*8
    const int tx   = tid & 15;            // 0..15 -> cols tx*4

    // A tile (128x16 = 512 float4): thread loads float4 idx tid and tid+256
    const int ar0 = tid >> 2;             // rows 0..63
    const int ar1 = 64 + ar0;             // rows 64..127
    const int ac  = (tid & 3) << 2;       // k-offset within tile {0,4,8,12}
    // B tile (16x64 = 256 float4): one per thread
    const int bkr = tid >> 4;             // k-row 0..15
    const int bcc = (tid & 15) << 2;      // col offset 0..60

    float acc[TM][TN];
#pragma unroll
    for (int i = 0; i < TM; i++)
#pragma unroll
        for (int j = 0; j < TN; j++) acc[i][j] = 0.0f;

    const float* Ap0 = A + (size_t)(brow + ar0) * K + ac;
    const float* Ap1 = A + (size_t)(brow + ar1) * K + ac;
    const float* Bp  = B + (size_t)bkr * N + bcol + bcc;

    float4 a0 = *(const float4*)(Ap0);
    float4 a1 = *(const float4*)(Ap1);
    float4 b0 = *(const float4*)(Bp);

    for (int k0 = 0; k0 < K; k0 += BK) {
        As[ac + 0][ar0] = a0.x; As[ac + 1][ar0] = a0.y;
        As[ac + 2][ar0] = a0.z; As[ac + 3][ar0] = a0.w;
        As[ac + 0][ar1] = a1.x; As[ac + 1][ar1] = a1.y;
        As[ac + 2][ar1] = a1.z; As[ac + 3][ar1] = a1.w;
        *(float4*)&Bs[bkr][bcc] = b0;
        __syncthreads();

        const int kn = k0 + BK;
        if (kn < K) {                     // prefetch next tile (hides GMEM latency)
            a0 = *(const float4*)(Ap0 + kn);
            a1 = *(const float4*)(Ap1 + kn);
            b0 = *(const float4*)(Bp + (size_t)kn * N);
        }

#pragma unroll
        for (int kk = 0; kk < BK; kk++) {
            float4 av0 = *(const float4*)&As[kk][ty * TM];
            float4 av1 = *(const float4*)&As[kk][ty * TM + 4];
            float4 bv  = *(const float4*)&Bs[kk][tx * TN];
            float a[8] = {av0.x, av0.y, av0.z, av0.w, av1.x, av1.y, av1.z, av1.w};
            float b[4] = {bv.x, bv.y, bv.z, bv.w};
#pragma unroll
            for (int i = 0; i < TM; i++)
#pragma unroll
                for (int j = 0; j < TN; j++)
                    acc[i][j] = fmaf(a[i], b[j], acc[i][j]);
        }
        __syncthreads();
    }

#pragma unroll
    for (int i = 0; i < TM; i++) {
        float4 v = make_float4(acc[i][0], acc[i][1], acc[i][2], acc[i][3]);
        if (DO_RELU) {
            v.x = fmaxf(v.x, 0.f); v.y = fmaxf(v.y, 0.f);
            v.z = fmaxf(v.z, 0.f); v.w = fmaxf(v.w, 0.f);
        }
        *(float4*)(C + (size_t)(brow + ty * TM + i) * N + bcol + tx * TN) = v;
    }
}

// ---------------- GCN branch helpers ---------------------------------------
__global__ void zero_kernel()
{
    int gid = blockIdx.x * 256 + threadIdx.x;
    if (gid < NN * DIM) g_Hl[gid] = 0.0f;
    if (gid < NN)       g_deg[gid] = 0;
}

// Detect whether edge_index is int64 (high words of first 256 entries all 0)
// or int32. Safe: reads only the first 1 MiB, valid under both layouts.
__global__ void detect_kernel(const int* __restrict__ ei32)
{
    if (blockIdx.x == 0 && threadIdx.x == 0) {
        int is64 = 1;
        for (int i = 0; i < 256; i++)
            if (ei32[2 * i + 1] != 0) { is64 = 0; break; }
        g_is64 = is64;
    }
}

__device__ __forceinline__ int edge_at(const void* ei, int pos, int is64)
{
    return is64 ? (int)((const long long*)ei)[pos] : ((const int*)ei)[pos];
}

__global__ void deg_kernel(const void* __restrict__ ei)
{
    int e = blockIdx.x * 256 + threadIdx.x;
    if (e >= NE) return;
    int d = edge_at(ei, NE + e, g_is64);
    atomicAdd(&g_deg[d], 1);
}

__global__ void dis_kernel()
{
    int n = blockIdx.x * 256 + threadIdx.x;
    if (n < NN) g_dis[n] = rsqrtf((float)(g_deg[n] + 1));   // +1 = self loop
}

// One thread per (edge, 4-col group): 4 coalesced float atomics into Hl[dst].
__global__ void scatter_kernel(const void* __restrict__ ei)
{
    int gid = blockIdx.x * 256 + threadIdx.x;
    int e = gid >> 6;
    if (e >= NE) return;
    int q = (gid & 63) << 2;
    int is64 = g_is64;
    int s = edge_at(ei, e, is64);
    int d = edge_at(ei, NE + e, is64);
    float coef = g_dis[s] * g_dis[d];
    float4 xw = *(const float4*)&g_XW[s * DIM + q];
    float* o = &g_Hl[d * DIM + q];
    atomicAdd(o + 0, coef * xw.x);
    atomicAdd(o + 1, coef * xw.y);
    atomicAdd(o + 2, coef * xw.z);
    atomicAdd(o + 3, coef * xw.w);
}

// out = aL * (Hl_scatter + dis[n]^2 * XW[n] + b_conv) + aH * Hh
__global__ void combine_kernel(const float* __restrict__ bc,
                               const float* __restrict__ aLp,
                               const float* __restrict__ aHp,
                               float* __restrict__ out)
{
    int gid = blockIdx.x * 256 + threadIdx.x;   // NN*64 threads
    int n = gid >> 6;
    int q = (gid & 63) << 2;
    float aL = aLp[0], aH = aHp[0];
    float ds = g_dis[n];
    float c2 = ds * ds;
    int idx = n * DIM + q;
    float4 hl = *(const float4*)&g_Hl[idx];
    float4 xw = *(const float4*)&g_XW[idx];
    float4 hh = *(const float4*)&g_Hh[idx];
    float4 b  = *(const float4*)&bc[q];
    float4 r;
    r.x = aL * (hl.x + c2 * xw.x + b.x) + aH * hh.x;
    r.y = aL * (hl.y + c2 * xw.y + b.y) + aH * hh.y;
    r.z = aL * (hl.z + c2 * xw.z + b.z) + aH * hh.z;
    r.w = aL * (hl.w + c2 * xw.w + b.w) + aH * hh.w;
    *(float4*)&out[idx] = r;
}

// ---------------- launch ----------------------------------------------------
extern "C" void kernel_launch(void* const* d_in, const int* in_sizes, int n_in,
                              void* d_out, int out_size)
{
    const float* x    = (const float*)d_in[0];
    const void*  ei   = d_in[1];
    const float* lap  = (const float*)d_in[2];
    const float* dinv = (const float*)d_in[3];
    const float* Wh   = (const float*)d_in[4];
    const float* Wc   = (const float*)d_in[5];
    const float* bc   = (const float*)d_in[6];
    const float* aL   = (const float*)d_in[7];
    const float* aH   = (const float*)d_in[8];
    float* out = (float*)d_out;

    float *T0, *T1, *T2, *Hh, *XW;
    cudaGetSymbolAddress((void**)&T0, g_T0);
    cudaGetSymbolAddress((void**)&T1, g_T1);
    cudaGetSymbolAddress((void**)&T2, g_T2);
    cudaGetSymbolAddress((void**)&Hh, g_Hh);
    cudaGetSymbolAddress((void**)&XW, g_XW);

    const dim3 gridG(DIM / 64, NN / 128);   // 4 x 32 = 128 CTAs

    zero_kernel<<<(NN * DIM) / 256, 256>>>();
    detect_kernel<<<1, 32>>>((const int*)ei);

    // small GEMMs (K = 256)
    gemm_n256<1><<<gridG, 256>>>(x, Wh, T0, DIM);   // T0 = relu(x @ W_high)
    gemm_n256<0><<<gridG, 256>>>(x, Wc, XW, DIM);   // XW = x @ W_conv

    // degrees / normalization
    deg_kernel<<<NE / 256, 256>>>(ei);
    dis_kernel<<<NN / 256, 256>>>();

    // high-pass branch, re-associated: d_inv @ (lap @ (d_inv @ T0))
    gemm_n256<0><<<gridG, 256>>>(dinv, T0, T1, NN);
    gemm_n256<0><<<gridG, 256>>>(lap,  T1, T2, NN);
    gemm_n256<0><<<gridG, 256>>>(dinv, T2, Hh, NN);

    // low-pass branch: message scatter
    scatter_kernel<<<(NE * 64) / 256, 256>>>(ei);

    // final combine
    combine_kernel<<<(NN * 64) / 256, 256>>>(bc, aL, aH, out);
}

// round 6
// speedup vs baseline: 1.4963x; 1.4963x over previous
#include <cuda_runtime.h>
#include <cuda_bf16.h>
#include <cstdint>

#define NN   4096
#define DIM  256
#define NE   131072

// ---------------- scratch (device globals: no allocation allowed) ----------
__device__ float g_T0[NN * DIM];   // relu(x @ W_high)
__device__ float g_T1[NN * DIM];   // d_inv @ T0
__device__ float g_T2[NN * DIM];   // lap @ T1
__device__ float g_Hh[NN * DIM];   // d_inv @ T2
__device__ float g_XW[NN * DIM];   // x @ W_conv
__device__ float g_Hl[NN * DIM];   // scatter accumulator
__device__ int   g_deg[NN];
__device__ float g_dis[NN];        // deg^{-1/2}
__device__ int   g_is64;           // edge_index dtype flag

// ---------------- tensor-core helpers --------------------------------------
__device__ __forceinline__ void ldsm_x4(uint32_t* r, const void* p)
{
    uint32_t a = (uint32_t)__cvta_generic_to_shared(p);
    asm volatile("ldmatrix.sync.aligned.m8n8.x4.shared.b16 {%0,%1,%2,%3},[%4];"
                 : "=r"(r[0]), "=r"(r[1]), "=r"(r[2]), "=r"(r[3]) : "r"(a));
}
__device__ __forceinline__ void ldsm_x4_t(uint32_t* r, const void* p)
{
    uint32_t a = (uint32_t)__cvta_generic_to_shared(p);
    asm volatile("ldmatrix.sync.aligned.m8n8.x4.trans.shared.b16 {%0,%1,%2,%3},[%4];"
                 : "=r"(r[0]), "=r"(r[1]), "=r"(r[2]), "=r"(r[3]) : "r"(a));
}
__device__ __forceinline__ void mma16816(float* c, const uint32_t* a, const uint32_t* b)
{
    asm volatile(
        "mma.sync.aligned.m16n8k16.row.col.f32.bf16.bf16.f32 "
        "{%0,%1,%2,%3},{%4,%5,%6,%7},{%8,%9},{%0,%1,%2,%3};"
        : "+f"(c[0]), "+f"(c[1]), "+f"(c[2]), "+f"(c[3])
        : "r"(a[0]), "r"(a[1]), "r"(a[2]), "r"(a[3]), "r"(b[0]), "r"(b[1]));
}

// split fp32 -> (hi, lo) bf16 pair
__device__ __forceinline__ void split2(float x, float y,
                                       __nv_bfloat162& hp, __nv_bfloat162& lp)
{
    __nv_bfloat16 hx = __float2bfloat16_rn(x);
    __nv_bfloat16 hy = __float2bfloat16_rn(y);
    float rx = x - __bfloat162float(hx);
    float ry = y - __bfloat162float(hy);
    hp.x = hx; hp.y = hy;
    lp.x = __float2bfloat16_rn(rx); lp.y = __float2bfloat16_rn(ry);
}

// ---------------- bf16x3 tensor-core GEMM ----------------------------------
// C[M,256] = A[M,K] @ B[K,256] with fp32 I/O, internal hi/lo bf16 split
// (acc += Ah*Bh + Ah*Bl + Al*Bh). BM=128, BN=64, BK=32, 256 threads,
// 8 warps laid out 4(M) x 2(N), warp tile 32x32 (2 m16 x 4 n8 mma tiles).
template <int DO_RELU>
__global__ __launch_bounds__(256)
void gemm_bf16x3(const float* __restrict__ A, const float* __restrict__ B,
                 float* __restrict__ C, int K)
{
    constexpr int BM = 128, BN = 64, BK = 32, N = 256;
    constexpr int SA = 40;   // A smem row stride (5 x 16B units -> conflict-free LDSM)
    constexpr int SB = 72;   // B smem row stride (9 x 16B units)
    __shared__ __align__(16) __nv_bfloat16 sAh[BM][SA];
    __shared__ __align__(16) __nv_bfloat16 sAl[BM][SA];
    __shared__ __align__(16) __nv_bfloat16 sBh[BK][SB];
    __shared__ __align__(16) __nv_bfloat16 sBl[BK][SB];

    const int tid  = threadIdx.x;
    const int lane = tid & 31;
    const int wid  = tid >> 5;
    const int wm   = wid >> 1;          // 0..3 -> warp rows wm*32
    const int wn   = wid & 1;           // 0..1 -> warp cols wn*32
    const int brow = blockIdx.y * BM;
    const int bcol = blockIdx.x * BN;

    // A tile: 128x32 fp32 = 1024 float4; thread handles 4 (row +32 per chunk)
    const int arow = tid >> 3;          // 0..31
    const int acol = (tid & 7) << 2;    // 0,4,..,28
    // B tile: 32x64 fp32 = 512 float4; thread handles 2 (row +16 per chunk)
    const int browB = tid >> 4;         // 0..15
    const int bcolB = (tid & 15) << 2;  // 0..60

    const float* Ap = A + (size_t)(brow + arow) * K + acol;
    const float* Bp = B + (size_t)browB * N + bcol + bcolB;

    float acc[2][4][4];
#pragma unroll
    for (int i = 0; i < 2; i++)
#pragma unroll
        for (int j = 0; j < 4; j++)
#pragma unroll
            for (int q = 0; q < 4; q++) acc[i][j][q] = 0.0f;

    float4 pa[4], pb[2];
#pragma unroll
    for (int j = 0; j < 4; j++) pa[j] = *(const float4*)(Ap + (size_t)(32 * j) * K);
#pragma unroll
    for (int j = 0; j < 2; j++) pb[j] = *(const float4*)(Bp + (size_t)(16 * j) * N);

    const int lrow  = lane & 15;
    const int lcolh = (lane >> 4) << 3;

    for (int k0 = 0; k0 < K; k0 += BK) {
        // stage with on-the-fly hi/lo split
#pragma unroll
        for (int j = 0; j < 4; j++) {
            int r = arow + 32 * j;
            __nv_bfloat162 h0, l0, h1, l1;
            split2(pa[j].x, pa[j].y, h0, l0);
            split2(pa[j].z, pa[j].w, h1, l1);
            *(__nv_bfloat162*)&sAh[r][acol]     = h0;
            *(__nv_bfloat162*)&sAh[r][acol + 2] = h1;
            *(__nv_bfloat162*)&sAl[r][acol]     = l0;
            *(__nv_bfloat162*)&sAl[r][acol + 2] = l1;
        }
#pragma unroll
        for (int j = 0; j < 2; j++) {
            int r = browB + 16 * j;
            __nv_bfloat162 h0, l0, h1, l1;
            split2(pb[j].x, pb[j].y, h0, l0);
            split2(pb[j].z, pb[j].w, h1, l1);
            *(__nv_bfloat162*)&sBh[r][bcolB]     = h0;
            *(__nv_bfloat162*)&sBh[r][bcolB + 2] = h1;
            *(__nv_bfloat162*)&sBl[r][bcolB]     = l0;
            *(__nv_bfloat162*)&sBl[r][bcolB + 2] = l1;
        }
        __syncthreads();

        const int kn = k0 + BK;
        if (kn < K) {                    // prefetch next tile into registers
#pragma unroll
            for (int j = 0; j < 4; j++)
                pa[j] = *(const float4*)(Ap + (size_t)(32 * j) * K + kn);
#pragma unroll
            for (int j = 0; j < 2; j++)
                pb[j] = *(const float4*)(Bp + (size_t)(16 * j) * N + (size_t)kn * N);
        }

#pragma unroll
        for (int kk = 0; kk < BK; kk += 16) {
            uint32_t ah[2][4], al[2][4], bh[2][4], bl[2][4];
#pragma unroll
            for (int mt = 0; mt < 2; mt++) {
                int r = wm * 32 + mt * 16 + lrow;
                ldsm_x4(ah[mt], &sAh[r][kk + lcolh]);
                ldsm_x4(al[mt], &sAl[r][kk + lcolh]);
            }
#pragma unroll
            for (int np = 0; np < 2; np++) {
                int c = wn * 32 + np * 16 + lcolh;
                ldsm_x4_t(bh[np], &sBh[kk + lrow][c]);
                ldsm_x4_t(bl[np], &sBl[kk + lrow][c]);
            }
#pragma unroll
            for (int mt = 0; mt < 2; mt++)
#pragma unroll
                for (int nt = 0; nt < 4; nt++) {
                    const uint32_t* bhp = &bh[nt >> 1][(nt & 1) * 2];
                    const uint32_t* blp = &bl[nt >> 1][(nt & 1) * 2];
                    mma16816(acc[mt][nt], ah[mt], bhp);   // Ah*Bh
                    mma16816(acc[mt][nt], ah[mt], blp);   // Ah*Bl
                    mma16816(acc[mt][nt], al[mt], bhp);   // Al*Bh
                }
        }
        __syncthreads();
    }

    // epilogue
    const int r0 = brow + wm * 32 + (lane >> 2);
    const int c0 = bcol + wn * 32 + ((lane & 3) << 1);
#pragma unroll
    for (int mt = 0; mt < 2; mt++)
#pragma unroll
        for (int nt = 0; nt < 4; nt++) {
            int row = r0 + mt * 16;
            int col = c0 + nt * 8;
            float2 v0 = make_float2(acc[mt][nt][0], acc[mt][nt][1]);
            float2 v1 = make_float2(acc[mt][nt][2], acc[mt][nt][3]);
            if (DO_RELU) {
                v0.x = fmaxf(v0.x, 0.f); v0.y = fmaxf(v0.y, 0.f);
                v1.x = fmaxf(v1.x, 0.f); v1.y = fmaxf(v1.y, 0.f);
            }
            *(float2*)(C + (size_t)row * N + col)       = v0;
            *(float2*)(C + (size_t)(row + 8) * N + col) = v1;
        }
}

// ---------------- GCN branch helpers ---------------------------------------
__global__ void zero_kernel()
{
    int gid = blockIdx.x * 256 + threadIdx.x;
    if (gid < NN * DIM) g_Hl[gid] = 0.0f;
    if (gid < NN)       g_deg[gid] = 0;
}

__global__ void detect_kernel(const int* __restrict__ ei32)
{
    if (blockIdx.x == 0 && threadIdx.x == 0) {
        int is64 = 1;
        for (int i = 0; i < 256; i++)
            if (ei32[2 * i + 1] != 0) { is64 = 0; break; }
        g_is64 = is64;
    }
}

__device__ __forceinline__ int edge_at(const void* ei, int pos, int is64)
{
    return is64 ? (int)((const long long*)ei)[pos] : ((const int*)ei)[pos];
}

__global__ void deg_kernel(const void* __restrict__ ei)
{
    int e = blockIdx.x * 256 + threadIdx.x;
    if (e >= NE) return;
    int d = edge_at(ei, NE + e, g_is64);
    atomicAdd(&g_deg[d], 1);
}

__global__ void dis_kernel()
{
    int n = blockIdx.x * 256 + threadIdx.x;
    if (n < NN) g_dis[n] = rsqrtf((float)(g_deg[n] + 1));   // +1 = self loop
}

// One thread per (edge, 4-col group): 4 coalesced float atomics into Hl[dst].
__global__ void scatter_kernel(const void* __restrict__ ei)
{
    int gid = blockIdx.x * 256 + threadIdx.x;
    int e = gid >> 6;
    if (e >= NE) return;
    int q = (gid & 63) << 2;
    int is64 = g_is64;
    int s = edge_at(ei, e, is64);
    int d = edge_at(ei, NE + e, is64);
    float coef = g_dis[s] * g_dis[d];
    float4 xw = *(const float4*)&g_XW[s * DIM + q];
    float* o = &g_Hl[d * DIM + q];
    atomicAdd(o + 0, coef * xw.x);
    atomicAdd(o + 1, coef * xw.y);
    atomicAdd(o + 2, coef * xw.z);
    atomicAdd(o + 3, coef * xw.w);
}

// out = aL * (Hl_scatter + dis[n]^2 * XW[n] + b_conv) + aH * Hh
__global__ void combine_kernel(const float* __restrict__ bc,
                               const float* __restrict__ aLp,
                               const float* __restrict__ aHp,
                               float* __restrict__ out)
{
    int gid = blockIdx.x * 256 + threadIdx.x;   // NN*64 threads
    int n = gid >> 6;
    int q = (gid & 63) << 2;
    float aL = aLp[0], aH = aHp[0];
    float ds = g_dis[n];
    float c2 = ds * ds;
    int idx = n * DIM + q;
    float4 hl = *(const float4*)&g_Hl[idx];
    float4 xw = *(const float4*)&g_XW[idx];
    float4 hh = *(const float4*)&g_Hh[idx];
    float4 b  = *(const float4*)&bc[q];
    float4 r;
    r.x = aL * (hl.x + c2 * xw.x + b.x) + aH * hh.x;
    r.y = aL * (hl.y + c2 * xw.y + b.y) + aH * hh.y;
    r.z = aL * (hl.z + c2 * xw.z + b.z) + aH * hh.z;
    r.w = aL * (hl.w + c2 * xw.w + b.w) + aH * hh.w;
    *(float4*)&out[idx] = r;
}

// ---------------- launch ----------------------------------------------------
extern "C" void kernel_launch(void* const* d_in, const int* in_sizes, int n_in,
                              void* d_out, int out_size)
{
    const float* x    = (const float*)d_in[0];
    const void*  ei   = d_in[1];
    const float* lap  = (const float*)d_in[2];
    const float* dinv = (const float*)d_in[3];
    const float* Wh   = (const float*)d_in[4];
    const float* Wc   = (const float*)d_in[5];
    const float* bc   = (const float*)d_in[6];
    const float* aL   = (const float*)d_in[7];
    const float* aH   = (const float*)d_in[8];
    float* out = (float*)d_out;

    float *T0, *T1, *T2, *Hh, *XW;
    cudaGetSymbolAddress((void**)&T0, g_T0);
    cudaGetSymbolAddress((void**)&T1, g_T1);
    cudaGetSymbolAddress((void**)&T2, g_T2);
    cudaGetSymbolAddress((void**)&Hh, g_Hh);
    cudaGetSymbolAddress((void**)&XW, g_XW);

    const dim3 gridG(DIM / 64, NN / 128);   // 4 x 32 = 128 CTAs

    zero_kernel<<<(NN * DIM) / 256, 256>>>();
    detect_kernel<<<1, 32>>>((const int*)ei);

    // small GEMMs (K = 256) on tensor cores too
    gemm_bf16x3<1><<<gridG, 256>>>(x, Wh, T0, DIM);   // T0 = relu(x @ W_high)
    gemm_bf16x3<0><<<gridG, 256>>>(x, Wc, XW, DIM);   // XW = x @ W_conv

    // degrees / normalization
    deg_kernel<<<NE / 256, 256>>>(ei);
    dis_kernel<<<NN / 256, 256>>>();

    // high-pass branch, re-associated: d_inv @ (lap @ (d_inv @ T0))
    gemm_bf16x3<0><<<gridG, 256>>>(dinv, T0, T1, NN);
    gemm_bf16x3<0><<<gridG, 256>>>(lap,  T1, T2, NN);
    gemm_bf16x3<0><<<gridG, 256>>>(dinv, T2, Hh, NN);

    // low-pass branch: message scatter
    scatter_kernel<<<(NE * 64) / 256, 256>>>(ei);

    // final combine
    combine_kernel<<<(NN * 64) / 256, 256>>>(bc, aL, aH, out);
}

// round 7
// speedup vs baseline: 2.1771x; 1.4550x over previous
#include <cuda_runtime.h>
#include <cuda_bf16.h>
#include <cstdint>

#define NN   4096
#define DIM  256
#define NE   131072

// ---------------- scratch (device globals: no allocation allowed) ----------
__device__ __nv_bfloat16 g_lapH[NN * NN], g_lapL[NN * NN];
__device__ __nv_bfloat16 g_dH[NN * NN],   g_dL[NN * NN];
__device__ __nv_bfloat16 g_xH[NN * DIM],  g_xL[NN * DIM];
__device__ __nv_bfloat16 g_WhH[DIM * DIM], g_WhL[DIM * DIM];
__device__ __nv_bfloat16 g_WcH[DIM * DIM], g_WcL[DIM * DIM];
__device__ __nv_bfloat16 g_T0H[NN * DIM], g_T0L[NN * DIM];
__device__ __nv_bfloat16 g_T1H[NN * DIM], g_T1L[NN * DIM];
__device__ __nv_bfloat16 g_T2H[NN * DIM], g_T2L[NN * DIM];
__device__ float g_Hh[NN * DIM];   // d_inv @ T2 (fp32)
__device__ float g_XW[NN * DIM];   // x @ W_conv (fp32)
__device__ float g_Hl[NN * DIM];   // scatter accumulator
__device__ int   g_deg[NN];
__device__ float g_dis[NN];        // deg^{-1/2}
__device__ int   g_is64;           // edge_index dtype flag

// ---------------- PTX helpers -----------------------------------------------
__device__ __forceinline__ void ldsm_x4(uint32_t* r, const void* p)
{
    uint32_t a = (uint32_t)__cvta_generic_to_shared(p);
    asm volatile("ldmatrix.sync.aligned.m8n8.x4.shared.b16 {%0,%1,%2,%3},[%4];"
                 : "=r"(r[0]), "=r"(r[1]), "=r"(r[2]), "=r"(r[3]) : "r"(a));
}
__device__ __forceinline__ void ldsm_x4_t(uint32_t* r, const void* p)
{
    uint32_t a = (uint32_t)__cvta_generic_to_shared(p);
    asm volatile("ldmatrix.sync.aligned.m8n8.x4.trans.shared.b16 {%0,%1,%2,%3},[%4];"
                 : "=r"(r[0]), "=r"(r[1]), "=r"(r[2]), "=r"(r[3]) : "r"(a));
}
__device__ __forceinline__ void mma16816(float* c, const uint32_t* a, const uint32_t* b)
{
    asm volatile(
        "mma.sync.aligned.m16n8k16.row.col.f32.bf16.bf16.f32 "
        "{%0,%1,%2,%3},{%4,%5,%6,%7},{%8,%9},{%0,%1,%2,%3};"
        : "+f"(c[0]), "+f"(c[1]), "+f"(c[2]), "+f"(c[3])
        : "r"(a[0]), "r"(a[1]), "r"(a[2]), "r"(a[3]), "r"(b[0]), "r"(b[1]));
}
__device__ __forceinline__ void cpa16(void* smem, const void* gmem)
{
    uint32_t s = (uint32_t)__cvta_generic_to_shared(smem);
    asm volatile("cp.async.cg.shared.global [%0],[%1],16;" :: "r"(s), "l"(gmem));
}
#define CP_COMMIT()   asm volatile("cp.async.commit_group;")
#define CP_WAIT(n)    asm volatile("cp.async.wait_group %0;" :: "n"(n))

// split fp32 -> (hi, lo) bf16 pair
__device__ __forceinline__ void split2(float x, float y,
                                       __nv_bfloat162& hp, __nv_bfloat162& lp)
{
    __nv_bfloat16 hx = __float2bfloat16_rn(x);
    __nv_bfloat16 hy = __float2bfloat16_rn(y);
    hp.x = hx; hp.y = hy;
    lp.x = __float2bfloat16_rn(x - __bfloat162float(hx));
    lp.y = __float2bfloat16_rn(y - __bfloat162float(hy));
}

// ---------------- pre-split conversion kernel -------------------------------
__global__ void split_mat(const float4* __restrict__ src,
                          uint2* __restrict__ h, uint2* __restrict__ l, int n4)
{
    int i = blockIdx.x * 256 + threadIdx.x;
    if (i >= n4) return;
    float4 v = src[i];
    __nv_bfloat162 h0, l0, h1, l1;
    split2(v.x, v.y, h0, l0);
    split2(v.z, v.w, h1, l1);
    h[i] = make_uint2(reinterpret_cast<uint32_t&>(h0), reinterpret_cast<uint32_t&>(h1));
    l[i] = make_uint2(reinterpret_cast<uint32_t&>(l0), reinterpret_cast<uint32_t&>(l1));
}

// ---------------- bf16x3 tensor-core GEMM, cp.async 3-stage pipeline --------
// C[M,256] = A @ B with pre-split bf16 hi/lo operands.
// acc += Ah*Bh + Ah*Bl + Al*Bh. BM=128, BN=64, BK=32, 256 threads,
// 8 warps 4(M) x 2(N), warp tile 32x32.
// EPI: 0 = fp32 out; 1 = bf16 hi/lo out; 2 = relu + bf16 hi/lo out.
template <int EPI>
__global__ __launch_bounds__(256)
void gemm_ts(const __nv_bfloat16* __restrict__ Ah, const __nv_bfloat16* __restrict__ Al,
             const __nv_bfloat16* __restrict__ Bh, const __nv_bfloat16* __restrict__ Bl,
             int K, float* __restrict__ Cf,
             __nv_bfloat16* __restrict__ Ch, __nv_bfloat16* __restrict__ Cl)
{
    constexpr int BM = 128, BN = 64, BK = 32, N = 256, S = 3;
    constexpr int SA = 40;                  // A row stride (5 x 16B units)
    constexpr int SB = 72;                  // B row stride (9 x 16B units)
    constexpr int AH_OFF = 0;
    constexpr int AL_OFF = BM * SA;         // 5120
    constexpr int BH_OFF = 2 * BM * SA;     // 10240
    constexpr int BL_OFF = BH_OFF + BK * SB;// 12544
    constexpr int STAGE  = BL_OFF + BK * SB;// 14848 bf16 / stage

    extern __shared__ __nv_bfloat16 smem[];

    const int tid  = threadIdx.x;
    const int lane = tid & 31;
    const int wid  = tid >> 5;
    const int wm   = wid >> 1;
    const int wn   = wid & 1;
    const int brow = blockIdx.y * BM;
    const int bcol = blockIdx.x * BN;

    // cp.async mapping: A tile 128x32 bf16 -> 512 16B chunks (h), thread does 2
    const int ar  = tid >> 2;               // 0..63
    const int ac8 = (tid & 3) << 3;         // 0,8,16,24
    // B tile 32x64 bf16 -> 256 chunks, thread does 1
    const int brB = tid >> 3;               // 0..31
    const int bc8 = (tid & 7) << 3;         // 0..56

    const size_t aoff0 = (size_t)(brow + ar) * K + ac8;
    const size_t aoff1 = (size_t)(brow + ar + 64) * K + ac8;

    auto load_stage = [&](int tile, int s) {
        __nv_bfloat16* sb = smem + s * STAGE;
        const int k0 = tile * BK;
        cpa16(sb + AH_OFF + ar * SA + ac8,        Ah + aoff0 + k0);
        cpa16(sb + AH_OFF + (ar + 64) * SA + ac8, Ah + aoff1 + k0);
        cpa16(sb + AL_OFF + ar * SA + ac8,        Al + aoff0 + k0);
        cpa16(sb + AL_OFF + (ar + 64) * SA + ac8, Al + aoff1 + k0);
        const size_t boff = (size_t)(k0 + brB) * N + bcol + bc8;
        cpa16(sb + BH_OFF + brB * SB + bc8, Bh + boff);
        cpa16(sb + BL_OFF + brB * SB + bc8, Bl + boff);
    };

    float acc[2][4][4];
#pragma unroll
    for (int i = 0; i < 2; i++)
#pragma unroll
        for (int j = 0; j < 4; j++)
#pragma unroll
            for (int q = 0; q < 4; q++) acc[i][j][q] = 0.0f;

    const int T = K / BK;
    load_stage(0, 0); CP_COMMIT();
    load_stage(1, 1); CP_COMMIT();

    const int lrow  = lane & 15;
    const int lcolh = (lane >> 4) << 3;

    for (int t = 0; t < T; t++) {
        CP_WAIT(1);            // oldest stage (t) landed
        __syncthreads();       // all warps: data visible, prev compute done
        if (t + S - 1 < T) { load_stage(t + S - 1, (t + S - 1) % S); CP_COMMIT(); }

        const __nv_bfloat16* sb = smem + (t % S) * STAGE;
#pragma unroll
        for (int kk = 0; kk < BK; kk += 16) {
            uint32_t ah[2][4], al[2][4], bh[2][4], bl[2][4];
#pragma unroll
            for (int mt = 0; mt < 2; mt++) {
                int r = wm * 32 + mt * 16 + lrow;
                ldsm_x4(ah[mt], sb + AH_OFF + r * SA + kk + lcolh);
                ldsm_x4(al[mt], sb + AL_OFF + r * SA + kk + lcolh);
            }
#pragma unroll
            for (int np = 0; np < 2; np++) {
                int c = wn * 32 + np * 16 + lcolh;
                ldsm_x4_t(bh[np], sb + BH_OFF + (kk + lrow) * SB + c);
                ldsm_x4_t(bl[np], sb + BL_OFF + (kk + lrow) * SB + c);
            }
#pragma unroll
            for (int mt = 0; mt < 2; mt++)
#pragma unroll
                for (int nt = 0; nt < 4; nt++) {
                    const uint32_t* bhp = &bh[nt >> 1][(nt & 1) * 2];
                    const uint32_t* blp = &bl[nt >> 1][(nt & 1) * 2];
                    mma16816(acc[mt][nt], ah[mt], bhp);
                    mma16816(acc[mt][nt], ah[mt], blp);
                    mma16816(acc[mt][nt], al[mt], bhp);
                }
        }
        __syncthreads();
    }

    // epilogue
    const int r0 = brow + wm * 32 + (lane >> 2);
    const int c0 = bcol + wn * 32 + ((lane & 3) << 1);
#pragma unroll
    for (int mt = 0; mt < 2; mt++)
#pragma unroll
        for (int nt = 0; nt < 4; nt++) {
            int row = r0 + mt * 16;
            int col = c0 + nt * 8;
            float2 v0 = make_float2(acc[mt][nt][0], acc[mt][nt][1]);
            float2 v1 = make_float2(acc[mt][nt][2], acc[mt][nt][3]);
            if (EPI == 2) {
                v0.x = fmaxf(v0.x, 0.f); v0.y = fmaxf(v0.y, 0.f);
                v1.x = fmaxf(v1.x, 0.f); v1.y = fmaxf(v1.y, 0.f);
            }
            if (EPI == 0) {
                *(float2*)(Cf + (size_t)row * N + col)       = v0;
                *(float2*)(Cf + (size_t)(row + 8) * N + col) = v1;
            } else {
                __nv_bfloat162 h0, l0, h1, l1;
                split2(v0.x, v0.y, h0, l0);
                split2(v1.x, v1.y, h1, l1);
                *(__nv_bfloat162*)(Ch + (size_t)row * N + col)       = h0;
                *(__nv_bfloat162*)(Cl + (size_t)row * N + col)       = l0;
                *(__nv_bfloat162*)(Ch + (size_t)(row + 8) * N + col) = h1;
                *(__nv_bfloat162*)(Cl + (size_t)(row + 8) * N + col) = l1;
            }
        }
}

// ---------------- GCN branch helpers ---------------------------------------
__global__ void zero_kernel()
{
    int gid = blockIdx.x * 256 + threadIdx.x;
    if (gid < NN * DIM) g_Hl[gid] = 0.0f;
    if (gid < NN)       g_deg[gid] = 0;
}

__global__ void detect_kernel(const int* __restrict__ ei32)
{
    if (blockIdx.x == 0 && threadIdx.x == 0) {
        int is64 = 1;
        for (int i = 0; i < 256; i++)
            if (ei32[2 * i + 1] != 0) { is64 = 0; break; }
        g_is64 = is64;
    }
}

__device__ __forceinline__ int edge_at(const void* ei, int pos, int is64)
{
    return is64 ? (int)((const long long*)ei)[pos] : ((const int*)ei)[pos];
}

__global__ void deg_kernel(const void* __restrict__ ei)
{
    int e = blockIdx.x * 256 + threadIdx.x;
    if (e >= NE) return;
    int d = edge_at(ei, NE + e, g_is64);
    atomicAdd(&g_deg[d], 1);
}

__global__ void dis_kernel()
{
    int n = blockIdx.x * 256 + threadIdx.x;
    if (n < NN) g_dis[n] = rsqrtf((float)(g_deg[n] + 1));   // +1 = self loop
}

// One thread per (edge, 4-col group): one float4 vector atomic into Hl[dst].
__global__ void scatter_kernel(const void* __restrict__ ei)
{
    int gid = blockIdx.x * 256 + threadIdx.x;
    int e = gid >> 6;
    if (e >= NE) return;
    int q = (gid & 63) << 2;
    int is64 = g_is64;
    int s = edge_at(ei, e, is64);
    int d = edge_at(ei, NE + e, is64);
    float coef = g_dis[s] * g_dis[d];
    float4 xw = *(const float4*)&g_XW[s * DIM + q];
    float4 m = make_float4(coef * xw.x, coef * xw.y, coef * xw.z, coef * xw.w);
    atomicAdd((float4*)&g_Hl[d * DIM + q], m);
}

// out = aL * (Hl_scatter + dis[n]^2 * XW[n] + b_conv) + aH * Hh
__global__ void combine_kernel(const float* __restrict__ bc,
                               const float* __restrict__ aLp,
                               const float* __restrict__ aHp,
                               float* __restrict__ out)
{
    int gid = blockIdx.x * 256 + threadIdx.x;   // NN*64 threads
    int n = gid >> 6;
    int q = (gid & 63) << 2;
    float aL = aLp[0], aH = aHp[0];
    float ds = g_dis[n];
    float c2 = ds * ds;
    int idx = n * DIM + q;
    float4 hl = *(const float4*)&g_Hl[idx];
    float4 xw = *(const float4*)&g_XW[idx];
    float4 hh = *(const float4*)&g_Hh[idx];
    float4 b  = *(const float4*)&bc[q];
    float4 r;
    r.x = aL * (hl.x + c2 * xw.x + b.x) + aH * hh.x;
    r.y = aL * (hl.y + c2 * xw.y + b.y) + aH * hh.y;
    r.z = aL * (hl.z + c2 * xw.z + b.z) + aH * hh.z;
    r.w = aL * (hl.w + c2 * xw.w + b.w) + aH * hh.w;
    *(float4*)&out[idx] = r;
}

// ---------------- launch ----------------------------------------------------
extern "C" void kernel_launch(void* const* d_in, const int* in_sizes, int n_in,
                              void* d_out, int out_size)
{
    const float* x    = (const float*)d_in[0];
    const void*  ei   = d_in[1];
    const float* lap  = (const float*)d_in[2];
    const float* dinv = (const float*)d_in[3];
    const float* Wh   = (const float*)d_in[4];
    const float* Wc   = (const float*)d_in[5];
    const float* bc   = (const float*)d_in[6];
    const float* aL   = (const float*)d_in[7];
    const float* aH   = (const float*)d_in[8];
    float* out = (float*)d_out;

    // symbol addresses
    __nv_bfloat16 *lapH, *lapL, *dH, *dL, *xH, *xL, *WhH, *WhL, *WcH, *WcL;
    __nv_bfloat16 *T0H, *T0L, *T1H, *T1L, *T2H, *T2L;
    float *Hh, *XW;
    cudaGetSymbolAddress((void**)&lapH, g_lapH); cudaGetSymbolAddress((void**)&lapL, g_lapL);
    cudaGetSymbolAddress((void**)&dH,  g_dH);    cudaGetSymbolAddress((void**)&dL,  g_dL);
    cudaGetSymbolAddress((void**)&xH,  g_xH);    cudaGetSymbolAddress((void**)&xL,  g_xL);
    cudaGetSymbolAddress((void**)&WhH, g_WhH);   cudaGetSymbolAddress((void**)&WhL, g_WhL);
    cudaGetSymbolAddress((void**)&WcH, g_WcH);   cudaGetSymbolAddress((void**)&WcL, g_WcL);
    cudaGetSymbolAddress((void**)&T0H, g_T0H);   cudaGetSymbolAddress((void**)&T0L, g_T0L);
    cudaGetSymbolAddress((void**)&T1H, g_T1H);   cudaGetSymbolAddress((void**)&T1L, g_T1L);
    cudaGetSymbolAddress((void**)&T2H, g_T2H);   cudaGetSymbolAddress((void**)&T2L, g_T2L);
    cudaGetSymbolAddress((void**)&Hh,  g_Hh);    cudaGetSymbolAddress((void**)&XW,  g_XW);

    constexpr int SMEM_BYTES = 3 * 14848 * 2;   // 89 KB dynamic smem
    static bool attr_set = false;
    if (!attr_set) {
        cudaFuncSetAttribute(gemm_ts<0>, cudaFuncAttributeMaxDynamicSharedMemorySize, SMEM_BYTES);
        cudaFuncSetAttribute(gemm_ts<1>, cudaFuncAttributeMaxDynamicSharedMemorySize, SMEM_BYTES);
        cudaFuncSetAttribute(gemm_ts<2>, cudaFuncAttributeMaxDynamicSharedMemorySize, SMEM_BYTES);
        attr_set = true;
    }

    const dim3 gridG(DIM / 64, NN / 128);   // 4 x 32 = 128 CTAs

    zero_kernel<<<(NN * DIM) / 256, 256>>>();
    detect_kernel<<<1, 32>>>((const int*)ei);

    // pre-split fp32 inputs into bf16 hi/lo
    split_mat<<<(NN * NN / 4) / 256, 256>>>((const float4*)lap,  (uint2*)lapH, (uint2*)lapL, NN * NN / 4);
    split_mat<<<(NN * NN / 4) / 256, 256>>>((const float4*)dinv, (uint2*)dH,   (uint2*)dL,   NN * NN / 4);
    split_mat<<<(NN * DIM / 4) / 256, 256>>>((const float4*)x,   (uint2*)xH,   (uint2*)xL,   NN * DIM / 4);
    split_mat<<<(DIM * DIM / 4 + 255) / 256, 256>>>((const float4*)Wh, (uint2*)WhH, (uint2*)WhL, DIM * DIM / 4);
    split_mat<<<(DIM * DIM / 4 + 255) / 256, 256>>>((const float4*)Wc, (uint2*)WcH, (uint2*)WcL, DIM * DIM / 4);

    // small GEMMs (K = 256)
    gemm_ts<2><<<gridG, 256, SMEM_BYTES>>>(xH, xL, WhH, WhL, DIM, nullptr, T0H, T0L); // relu(x@Wh) -> split
    gemm_ts<0><<<gridG, 256, SMEM_BYTES>>>(xH, xL, WcH, WcL, DIM, XW, nullptr, nullptr);

    // degrees / normalization
    deg_kernel<<<NE / 256, 256>>>(ei);
    dis_kernel<<<NN / 256, 256>>>();

    // high-pass branch chain: d_inv @ (lap @ (d_inv @ T0))
    gemm_ts<1><<<gridG, 256, SMEM_BYTES>>>(dH, dL, T0H, T0L, NN, nullptr, T1H, T1L);
    gemm_ts<1><<<gridG, 256, SMEM_BYTES>>>(lapH, lapL, T1H, T1L, NN, nullptr, T2H, T2L);
    gemm_ts<0><<<gridG, 256, SMEM_BYTES>>>(dH, dL, T2H, T2L, NN, Hh, nullptr, nullptr);

    // low-pass branch: message scatter (float4 vector atomics)
    scatter_kernel<<<(NE * 64) / 256, 256>>>(ei);

    // final combine
    combine_kernel<<<(NN * 64) / 256, 256>>>(bc, aL, aH, out);
}

// round 10
// speedup vs baseline: 2.7097x; 1.2446x over previous
#include <cuda_runtime.h>
#include <cuda_bf16.h>
#include <cstdint>

#define NN   4096
#define DIM  256
#define NE   131072

// ---------------- scratch (device globals: no allocation allowed) ----------
__device__ __nv_bfloat16 g_lapH[NN * NN], g_lapL[NN * NN];
__device__ __nv_bfloat16 g_dH[NN * NN],   g_dL[NN * NN];
__device__ __nv_bfloat16 g_xH[NN * DIM],  g_xL[NN * DIM];
__device__ __nv_bfloat16 g_WhH[DIM * DIM], g_WhL[DIM * DIM];
__device__ __nv_bfloat16 g_WcH[DIM * DIM], g_WcL[DIM * DIM];
__device__ __nv_bfloat16 g_T0H[NN * DIM], g_T0L[NN * DIM];
__device__ __nv_bfloat16 g_T1H[NN * DIM], g_T1L[NN * DIM];
__device__ __nv_bfloat16 g_T2H[NN * DIM], g_T2L[NN * DIM];
__device__ float g_Hh[NN * DIM];
__device__ float g_XW[NN * DIM];
__device__ float g_Hl[NN * DIM];
__device__ int   g_deg[NN];
__device__ float g_dis[NN];
__device__ int   g_is64;

// ---------------- PTX helpers -----------------------------------------------
__device__ __forceinline__ uint32_t smem_u32(const void* p)
{
    uint32_t a;
    asm("{ .reg .u64 t; cvta.to.shared.u64 t, %1; cvt.u32.u64 %0, t; }"
        : "=r"(a) : "l"(p));
    return a;
}
__device__ __forceinline__ void ldsm_x4(uint32_t* r, uint32_t a)
{
    asm volatile("ldmatrix.sync.aligned.m8n8.x4.shared.b16 {%0,%1,%2,%3},[%4];"
                 : "=r"(r[0]), "=r"(r[1]), "=r"(r[2]), "=r"(r[3]) : "r"(a));
}
__device__ __forceinline__ void ldsm_x4_t(uint32_t* r, uint32_t a)
{
    asm volatile("ldmatrix.sync.aligned.m8n8.x4.trans.shared.b16 {%0,%1,%2,%3},[%4];"
                 : "=r"(r[0]), "=r"(r[1]), "=r"(r[2]), "=r"(r[3]) : "r"(a));
}
__device__ __forceinline__ void mma16816(float* c, const uint32_t* a, const uint32_t* b)
{
    asm volatile(
        "mma.sync.aligned.m16n8k16.row.col.f32.bf16.bf16.f32 "
        "{%0,%1,%2,%3},{%4,%5,%6,%7},{%8,%9},{%0,%1,%2,%3};"
        : "+f"(c[0]), "+f"(c[1]), "+f"(c[2]), "+f"(c[3])
        : "r"(a[0]), "r"(a[1]), "r"(a[2]), "r"(a[3]), "r"(b[0]), "r"(b[1]));
}
__device__ __forceinline__ void cpa16(uint32_t smem, const void* gmem)
{
    asm volatile("cp.async.cg.shared.global [%0],[%1],16;" :: "r"(smem), "l"(gmem));
}
#define CP_COMMIT() asm volatile("cp.async.commit_group;")
#define CP_WAIT(n)  asm volatile("cp.async.wait_group %0;" :: "n"(n))

// split fp32 -> (hi, lo) bf16
__device__ __forceinline__ void split1(float v, __nv_bfloat16& h, __nv_bfloat16& l)
{
    h = __float2bfloat16_rn(v);
    l = __float2bfloat16_rn(v - __bfloat162float(h));
}
__device__ __forceinline__ void split2(float x, float y,
                                       __nv_bfloat162& hp, __nv_bfloat162& lp)
{
    split1(x, hp.x, lp.x);
    split1(y, hp.y, lp.y);
}

// ---------------- conversion kernel -----------------------------------------
__global__ void split_mat(const float4* __restrict__ src,
                          uint2* __restrict__ h, uint2* __restrict__ l, int n4)
{
    int i = blockIdx.x * 256 + threadIdx.x;
    if (i >= n4) return;
    float4 v = src[i];
    __nv_bfloat162 h0, l0, h1, l1;
    split2(v.x, v.y, h0, l0);
    split2(v.z, v.w, h1, l1);
    h[i] = make_uint2(reinterpret_cast<uint32_t&>(h0), reinterpret_cast<uint32_t&>(h1));
    l[i] = make_uint2(reinterpret_cast<uint32_t&>(l0), reinterpret_cast<uint32_t&>(l1));
}

// ---------------- bf16x3 mma.sync GEMM, BK=64, reg-double-buffered ----------
// C[M,256] = A[M,K] @ B[K,256]; A/B pre-split bf16 hi/lo, natural layouts.
// acc += Ah*Bh + Ah*Bl + Al*Bh. BM=128, BN=64, BK=64, 256 threads,
// 8 warps 4(M) x 2(N), warp tile 32x32. XOR-swizzled 128B smem rows.
// EPI: 0 = fp32 out; 1 = bf16 hi/lo out; 2 = relu + bf16 hi/lo out.
template <int EPI>
__global__ __launch_bounds__(256)
void gemm_mm(const __nv_bfloat16* __restrict__ Ah, const __nv_bfloat16* __restrict__ Al,
             const __nv_bfloat16* __restrict__ Bh, const __nv_bfloat16* __restrict__ Bl,
             int K, float* __restrict__ Cf,
             __nv_bfloat16* __restrict__ Ch, __nv_bfloat16* __restrict__ Cl)
{
    constexpr int BM = 128, BN = 64, BK = 64, N = 256, S = 3;
    constexpr int AL_OFF = 16384;          // A: 128 rows x 128B
    constexpr int BH_OFF = 32768;          // B: 64 k-rows x 128B
    constexpr int BL_OFF = 40960;
    constexpr int STAGE  = 49152;          // 48 KB per stage

    extern __shared__ __align__(1024) char dsm[];
    const uint32_t sbase = smem_u32(dsm);

    const int tid  = threadIdx.x;
    const int lane = tid & 31;
    const int wid  = tid >> 5;
    const int wm   = wid >> 1;             // 0..3 -> warp rows wm*32
    const int wn   = wid & 1;              // 0..1 -> warp cols wn*32
    const int brow = blockIdx.y * BM;
    const int bcol = blockIdx.x * BN;

    // cp.async mapping: 16B chunks, XOR swizzle on 128B rows
    const int r0   = tid >> 3;             // 0..31
    const int cb   = (tid & 7) * 16;       // byte chunk in row
    const int kkel = (tid & 7) * 8;        // element offset

    auto load_stage = [&](int tk, int s) {
        const uint32_t st = sbase + s * STAGE;
        const int k0 = tk * BK;
#pragma unroll
        for (int i = 0; i < 4; i++) {      // A: 128 rows
            int row = r0 + 32 * i;
            uint32_t off = row * 128 + cb;
            off ^= ((off >> 3) & 0x70);
            const size_t g = (size_t)(brow + row) * K + k0 + kkel;
            cpa16(st + off,          Ah + g);
            cpa16(st + AL_OFF + off, Al + g);
        }
#pragma unroll
        for (int i = 0; i < 2; i++) {      // B: 64 k-rows
            int kr = r0 + 32 * i;
            uint32_t off = kr * 128 + cb;
            off ^= ((off >> 3) & 0x70);
            const size_t g = (size_t)(k0 + kr) * N + bcol + kkel;
            cpa16(st + BH_OFF + off, Bh + g);
            cpa16(st + BL_OFF + off, Bl + g);
        }
        CP_COMMIT();
    };

    float acc[2][4][4];
#pragma unroll
    for (int i = 0; i < 2; i++)
#pragma unroll
        for (int j = 0; j < 4; j++)
#pragma unroll
            for (int q = 0; q < 4; q++) acc[i][j][q] = 0.0f;

    // fragment double buffers
    uint32_t ah[2][2][4], al[2][2][4], bh[2][2][4], bl[2][2][4];

    const int lrow  = lane & 15;
    const int lcolh = (lane >> 4) << 3;

    auto ldfrag = [&](uint32_t st, int kc, int buf) {
#pragma unroll
        for (int mt = 0; mt < 2; mt++) {
            int r = wm * 32 + mt * 16 + lrow;
            uint32_t off = r * 128 + (kc * 16 + lcolh) * 2;
            off ^= ((off >> 3) & 0x70);
            ldsm_x4(ah[buf][mt], st + off);
            ldsm_x4(al[buf][mt], st + AL_OFF + off);
        }
#pragma unroll
        for (int np = 0; np < 2; np++) {
            int kr = kc * 16 + lrow;
            int c  = wn * 32 + np * 16 + lcolh;
            uint32_t off = kr * 128 + c * 2;
            off ^= ((off >> 3) & 0x70);
            ldsm_x4_t(bh[buf][np], st + BH_OFF + off);
            ldsm_x4_t(bl[buf][np], st + BL_OFF + off);
        }
    };

    auto mma_chunk = [&](int buf) {
#pragma unroll
        for (int mt = 0; mt < 2; mt++)
#pragma unroll
            for (int nt = 0; nt < 4; nt++) {
                const uint32_t* bhp = &bh[buf][nt >> 1][(nt & 1) * 2];
                const uint32_t* blp = &bl[buf][nt >> 1][(nt & 1) * 2];
                mma16816(acc[mt][nt], ah[buf][mt], bhp);
                mma16816(acc[mt][nt], ah[buf][mt], blp);
                mma16816(acc[mt][nt], al[buf][mt], bhp);
            }
    };

    const int T = K / BK;
    load_stage(0, 0);
    load_stage(1, 1);

    for (int t = 0; t < T; t++) {
        if (t < T - 1) CP_WAIT(1); else CP_WAIT(0);   // stage t landed
        __syncthreads();                               // + prev tile compute done
        if (t + 2 < T) load_stage(t + 2, (t + 2) % S);

        const uint32_t st = sbase + (t % S) * STAGE;
        ldfrag(st, 0, 0);
#pragma unroll
        for (int kc = 0; kc < 4; kc++) {
            if (kc < 3) ldfrag(st, kc + 1, (kc + 1) & 1);  // hide LDS latency
            mma_chunk(kc & 1);
        }
        __syncthreads();
    }

    // epilogue (natural [M,256] layout, coalesced)
    const int rr0 = brow + wm * 32 + (lane >> 2);
    const int cc0 = bcol + wn * 32 + ((lane & 3) << 1);
#pragma unroll
    for (int mt = 0; mt < 2; mt++)
#pragma unroll
        for (int nt = 0; nt < 4; nt++) {
            int row = rr0 + mt * 16;
            int col = cc0 + nt * 8;
            float2 v0 = make_float2(acc[mt][nt][0], acc[mt][nt][1]);
            float2 v1 = make_float2(acc[mt][nt][2], acc[mt][nt][3]);
            if (EPI == 2) {
                v0.x = fmaxf(v0.x, 0.f); v0.y = fmaxf(v0.y, 0.f);
                v1.x = fmaxf(v1.x, 0.f); v1.y = fmaxf(v1.y, 0.f);
            }
            if (EPI == 0) {
                *(float2*)(Cf + (size_t)row * N + col)       = v0;
                *(float2*)(Cf + (size_t)(row + 8) * N + col) = v1;
            } else {
                __nv_bfloat162 h0, l0, h1, l1;
                split2(v0.x, v0.y, h0, l0);
                split2(v1.x, v1.y, h1, l1);
                *(__nv_bfloat162*)(Ch + (size_t)row * N + col)       = h0;
                *(__nv_bfloat162*)(Cl + (size_t)row * N + col)       = l0;
                *(__nv_bfloat162*)(Ch + (size_t)(row + 8) * N + col) = h1;
                *(__nv_bfloat162*)(Cl + (size_t)(row + 8) * N + col) = l1;
            }
        }
}

// ---------------- GCN branch helpers ---------------------------------------
__global__ void zero_kernel()
{
    int gid = blockIdx.x * 256 + threadIdx.x;
    if (gid < NN * DIM) g_Hl[gid] = 0.0f;
    if (gid < NN)       g_deg[gid] = 0;
}

__global__ void detect_kernel(const int* __restrict__ ei32)
{
    if (blockIdx.x == 0 && threadIdx.x == 0) {
        int is64 = 1;
        for (int i = 0; i < 256; i++)
            if (ei32[2 * i + 1] != 0) { is64 = 0; break; }
        g_is64 = is64;
    }
}

__device__ __forceinline__ int edge_at(const void* ei, int pos, int is64)
{
    return is64 ? (int)((const long long*)ei)[pos] : ((const int*)ei)[pos];
}

__global__ void deg_kernel(const void* __restrict__ ei)
{
    int e = blockIdx.x * 256 + threadIdx.x;
    if (e >= NE) return;
    int d = edge_at(ei, NE + e, g_is64);
    atomicAdd(&g_deg[d], 1);
}

__global__ void dis_kernel()
{
    int n = blockIdx.x * 256 + threadIdx.x;
    if (n < NN) g_dis[n] = rsqrtf((float)(g_deg[n] + 1));
}

__global__ void scatter_kernel(const void* __restrict__ ei)
{
    int gid = blockIdx.x * 256 + threadIdx.x;
    int e = gid >> 6;
    if (e >= NE) return;
    int q = (gid & 63) << 2;
    int is64 = g_is64;
    int s = edge_at(ei, e, is64);
    int d = edge_at(ei, NE + e, is64);
    float coef = g_dis[s] * g_dis[d];
    float4 xw = *(const float4*)&g_XW[s * DIM + q];
    float4 m = make_float4(coef * xw.x, coef * xw.y, coef * xw.z, coef * xw.w);
    atomicAdd((float4*)&g_Hl[d * DIM + q], m);
}

__global__ void combine_kernel(const float* __restrict__ bc,
                               const float* __restrict__ aLp,
                               const float* __restrict__ aHp,
                               float* __restrict__ out)
{
    int gid = blockIdx.x * 256 + threadIdx.x;
    int n = gid >> 6;
    int q = (gid & 63) << 2;
    float aL = aLp[0], aH = aHp[0];
    float ds = g_dis[n];
    float c2 = ds * ds;
    int idx = n * DIM + q;
    float4 hl = *(const float4*)&g_Hl[idx];
    float4 xw = *(const float4*)&g_XW[idx];
    float4 hh = *(const float4*)&g_Hh[idx];
    float4 b  = *(const float4*)&bc[q];
    float4 r;
    r.x = aL * (hl.x + c2 * xw.x + b.x) + aH * hh.x;
    r.y = aL * (hl.y + c2 * xw.y + b.y) + aH * hh.y;
    r.z = aL * (hl.z + c2 * xw.z + b.z) + aH * hh.z;
    r.w = aL * (hl.w + c2 * xw.w + b.w) + aH * hh.w;
    *(float4*)&out[idx] = r;
}

// ---------------- launch ----------------------------------------------------
extern "C" void kernel_launch(void* const* d_in, const int* in_sizes, int n_in,
                              void* d_out, int out_size)
{
    const float* x    = (const float*)d_in[0];
    const void*  ei   = d_in[1];
    const float* lap  = (const float*)d_in[2];
    const float* dinv = (const float*)d_in[3];
    const float* Wh   = (const float*)d_in[4];
    const float* Wc   = (const float*)d_in[5];
    const float* bc   = (const float*)d_in[6];
    const float* aL   = (const float*)d_in[7];
    const float* aH   = (const float*)d_in[8];
    float* out = (float*)d_out;

    __nv_bfloat16 *lapH, *lapL, *dH, *dL, *xH, *xL, *WhH, *WhL, *WcH, *WcL;
    __nv_bfloat16 *T0H, *T0L, *T1H, *T1L, *T2H, *T2L;
    float *Hh, *XW;
    cudaGetSymbolAddress((void**)&lapH, g_lapH); cudaGetSymbolAddress((void**)&lapL, g_lapL);
    cudaGetSymbolAddress((void**)&dH,   g_dH);   cudaGetSymbolAddress((void**)&dL,   g_dL);
    cudaGetSymbolAddress((void**)&xH,   g_xH);   cudaGetSymbolAddress((void**)&xL,   g_xL);
    cudaGetSymbolAddress((void**)&WhH,  g_WhH);  cudaGetSymbolAddress((void**)&WhL,  g_WhL);
    cudaGetSymbolAddress((void**)&WcH,  g_WcH);  cudaGetSymbolAddress((void**)&WcL,  g_WcL);
    cudaGetSymbolAddress((void**)&T0H,  g_T0H);  cudaGetSymbolAddress((void**)&T0L,  g_T0L);
    cudaGetSymbolAddress((void**)&T1H,  g_T1H);  cudaGetSymbolAddress((void**)&T1L,  g_T1L);
    cudaGetSymbolAddress((void**)&T2H,  g_T2H);  cudaGetSymbolAddress((void**)&T2L,  g_T2L);
    cudaGetSymbolAddress((void**)&Hh,   g_Hh);   cudaGetSymbolAddress((void**)&XW,   g_XW);

    constexpr int SMEM_BYTES = 3 * 49152;   // 144 KB dynamic smem
    static bool attr_set = false;
    if (!attr_set) {
        cudaFuncSetAttribute(gemm_mm<0>, cudaFuncAttributeMaxDynamicSharedMemorySize, SMEM_BYTES);
        cudaFuncSetAttribute(gemm_mm<1>, cudaFuncAttributeMaxDynamicSharedMemorySize, SMEM_BYTES);
        cudaFuncSetAttribute(gemm_mm<2>, cudaFuncAttributeMaxDynamicSharedMemorySize, SMEM_BYTES);
        attr_set = true;
    }

    const dim3 gridG(DIM / 64, NN / 128);   // 4 x 32 = 128 CTAs

    zero_kernel<<<(NN * DIM) / 256, 256>>>();
    detect_kernel<<<1, 32>>>((const int*)ei);

    // pre-split fp32 inputs into bf16 hi/lo (all natural layouts)
    split_mat<<<(NN * NN / 4) / 256, 256>>>((const float4*)lap,  (uint2*)lapH, (uint2*)lapL, NN * NN / 4);
    split_mat<<<(NN * NN / 4) / 256, 256>>>((const float4*)dinv, (uint2*)dH,   (uint2*)dL,   NN * NN / 4);
    split_mat<<<(NN * DIM / 4) / 256, 256>>>((const float4*)x,   (uint2*)xH,   (uint2*)xL,   NN * DIM / 4);
    split_mat<<<(DIM * DIM / 4 + 255) / 256, 256>>>((const float4*)Wh, (uint2*)WhH, (uint2*)WhL, DIM * DIM / 4);
    split_mat<<<(DIM * DIM / 4 + 255) / 256, 256>>>((const float4*)Wc, (uint2*)WcH, (uint2*)WcL, DIM * DIM / 4);

    // small GEMMs (K = 256)
    gemm_mm<2><<<gridG, 256, SMEM_BYTES>>>(xH, xL, WhH, WhL, DIM, nullptr, T0H, T0L);
    gemm_mm<0><<<gridG, 256, SMEM_BYTES>>>(xH, xL, WcH, WcL, DIM, XW, nullptr, nullptr);

    // degrees / normalization
    deg_kernel<<<NE / 256, 256>>>(ei);
    dis_kernel<<<NN / 256, 256>>>();

    // high-pass chain: d_inv @ (lap @ (d_inv @ T0))
    gemm_mm<1><<<gridG, 256, SMEM_BYTES>>>(dH,   dL,   T0H, T0L, NN, nullptr, T1H, T1L);
    gemm_mm<1><<<gridG, 256, SMEM_BYTES>>>(lapH, lapL, T1H, T1L, NN, nullptr, T2H, T2L);
    gemm_mm<0><<<gridG, 256, SMEM_BYTES>>>(dH,   dL,   T2H, T2L, NN, Hh, nullptr, nullptr);

    // low-pass branch: message scatter
    scatter_kernel<<<(NE * 64) / 256, 256>>>(ei);

    // final combine
    combine_kernel<<<(NN * 64) / 256, 256>>>(bc, aL, aH, out);
}

// round 11
// speedup vs baseline: 2.8270x; 1.0433x over previous
#include <cuda_runtime.h>
#include <cuda_bf16.h>
#include <cstdint>

#define NN   4096
#define DIM  256
#define NE   131072

// ---------------- scratch (device globals: no allocation allowed) ----------
__device__ __nv_bfloat16 g_lapH[NN * NN], g_lapL[NN * NN];
__device__ __nv_bfloat16 g_dH[NN * NN],   g_dL[NN * NN];
__device__ __nv_bfloat16 g_xH[NN * DIM],  g_xL[NN * DIM];
__device__ __nv_bfloat16 g_WhH[DIM * DIM], g_WhL[DIM * DIM];
__device__ __nv_bfloat16 g_WcH[DIM * DIM], g_WcL[DIM * DIM];
__device__ __nv_bfloat16 g_T0H[NN * DIM], g_T0L[NN * DIM];
__device__ __nv_bfloat16 g_T1H[NN * DIM], g_T1L[NN * DIM];
__device__ __nv_bfloat16 g_T2H[NN * DIM], g_T2L[NN * DIM];
__device__ float g_XW[NN * DIM];
__device__ float g_Hl[NN * DIM];
__device__ int   g_deg[NN];
__device__ float g_dis[NN];
__device__ int   g_is64;

// ---------------- PTX helpers -----------------------------------------------
__device__ __forceinline__ uint32_t smem_u32(const void* p)
{
    uint32_t a;
    asm("{ .reg .u64 t; cvta.to.shared.u64 t, %1; cvt.u32.u64 %0, t; }"
        : "=r"(a) : "l"(p));
    return a;
}
__device__ __forceinline__ void ldsm_x4(uint32_t* r, uint32_t a)
{
    asm volatile("ldmatrix.sync.aligned.m8n8.x4.shared.b16 {%0,%1,%2,%3},[%4];"
                 : "=r"(r[0]), "=r"(r[1]), "=r"(r[2]), "=r"(r[3]) : "r"(a));
}
__device__ __forceinline__ void ldsm_x4_t(uint32_t* r, uint32_t a)
{
    asm volatile("ldmatrix.sync.aligned.m8n8.x4.trans.shared.b16 {%0,%1,%2,%3},[%4];"
                 : "=r"(r[0]), "=r"(r[1]), "=r"(r[2]), "=r"(r[3]) : "r"(a));
}
__device__ __forceinline__ void mma16816(float* c, const uint32_t* a, const uint32_t* b)
{
    asm volatile(
        "mma.sync.aligned.m16n8k16.row.col.f32.bf16.bf16.f32 "
        "{%0,%1,%2,%3},{%4,%5,%6,%7},{%8,%9},{%0,%1,%2,%3};"
        : "+f"(c[0]), "+f"(c[1]), "+f"(c[2]), "+f"(c[3])
        : "r"(a[0]), "r"(a[1]), "r"(a[2]), "r"(a[3]), "r"(b[0]), "r"(b[1]));
}
__device__ __forceinline__ void cpa16(uint32_t smem, const void* gmem)
{
    asm volatile("cp.async.cg.shared.global [%0],[%1],16;" :: "r"(smem), "l"(gmem));
}
#define CP_COMMIT() asm volatile("cp.async.commit_group;")
#define CP_WAIT(n)  asm volatile("cp.async.wait_group %0;" :: "n"(n))

// split fp32 -> (hi, lo) bf16
__device__ __forceinline__ void split1(float v, __nv_bfloat16& h, __nv_bfloat16& l)
{
    h = __float2bfloat16_rn(v);
    l = __float2bfloat16_rn(v - __bfloat162float(h));
}
__device__ __forceinline__ void split2(float x, float y,
                                       __nv_bfloat162& hp, __nv_bfloat162& lp)
{
    split1(x, hp.x, lp.x);
    split1(y, hp.y, lp.y);
}

// ---------------- conversion kernel -----------------------------------------
__global__ void split_mat(const float4* __restrict__ src,
                          uint2* __restrict__ h, uint2* __restrict__ l, int n4)
{
    int i = blockIdx.x * 256 + threadIdx.x;
    if (i >= n4) return;
    float4 v = src[i];
    __nv_bfloat162 h0, l0, h1, l1;
    split2(v.x, v.y, h0, l0);
    split2(v.z, v.w, h1, l1);
    h[i] = make_uint2(reinterpret_cast<uint32_t&>(h0), reinterpret_cast<uint32_t&>(h1));
    l[i] = make_uint2(reinterpret_cast<uint32_t&>(l0), reinterpret_cast<uint32_t&>(l1));
}

// ---------------- bf16x3 mma.sync GEMM, BK=64, reg-double-buffered ----------
// C[M,256] = A[M,K] @ B[K,256]; A/B pre-split bf16 hi/lo, natural layouts.
// acc += Ah*Bh + Ah*Bl + Al*Bh. BM=128, BN=64, BK=64, 256 threads,
// 8 warps 4(M) x 2(N), warp tile 32x32. XOR-swizzled 128B smem rows.
// EPI: 0 = fp32 out; 1 = bf16 hi/lo out; 2 = relu + bf16 hi/lo out;
//      3 = fused FBGCN combine: out = aL*(Hl + dis^2*XW + bc) + aH*acc.
template <int EPI>
__global__ __launch_bounds__(256)
void gemm_mm(const __nv_bfloat16* __restrict__ Ah, const __nv_bfloat16* __restrict__ Al,
             const __nv_bfloat16* __restrict__ Bh, const __nv_bfloat16* __restrict__ Bl,
             int K, float* __restrict__ Cf,
             __nv_bfloat16* __restrict__ Ch, __nv_bfloat16* __restrict__ Cl,
             const float* __restrict__ bc, const float* __restrict__ aLp,
             const float* __restrict__ aHp)
{
    constexpr int BM = 128, BN = 64, BK = 64, N = 256, S = 3;
    constexpr int AL_OFF = 16384;          // A: 128 rows x 128B
    constexpr int BH_OFF = 32768;          // B: 64 k-rows x 128B
    constexpr int BL_OFF = 40960;
    constexpr int STAGE  = 49152;          // 48 KB per stage

    extern __shared__ __align__(1024) char dsm[];
    const uint32_t sbase = smem_u32(dsm);

    const int tid  = threadIdx.x;
    const int lane = tid & 31;
    const int wid  = tid >> 5;
    const int wm   = wid >> 1;
    const int wn   = wid & 1;
    const int brow = blockIdx.y * BM;
    const int bcol = blockIdx.x * BN;

    const int r0   = tid >> 3;
    const int cb   = (tid & 7) * 16;
    const int kkel = (tid & 7) * 8;

    auto load_stage = [&](int tk, int s) {
        const uint32_t st = sbase + s * STAGE;
        const int k0 = tk * BK;
#pragma unroll
        for (int i = 0; i < 4; i++) {
            int row = r0 + 32 * i;
            uint32_t off = row * 128 + cb;
            off ^= ((off >> 3) & 0x70);
            const size_t g = (size_t)(brow + row) * K + k0 + kkel;
            cpa16(st + off,          Ah + g);
            cpa16(st + AL_OFF + off, Al + g);
        }
#pragma unroll
        for (int i = 0; i < 2; i++) {
            int kr = r0 + 32 * i;
            uint32_t off = kr * 128 + cb;
            off ^= ((off >> 3) & 0x70);
            const size_t g = (size_t)(k0 + kr) * N + bcol + kkel;
            cpa16(st + BH_OFF + off, Bh + g);
            cpa16(st + BL_OFF + off, Bl + g);
        }
        CP_COMMIT();
    };

    float acc[2][4][4];
#pragma unroll
    for (int i = 0; i < 2; i++)
#pragma unroll
        for (int j = 0; j < 4; j++)
#pragma unroll
            for (int q = 0; q < 4; q++) acc[i][j][q] = 0.0f;

    uint32_t ah[2][2][4], al[2][2][4], bh[2][2][4], bl[2][2][4];
    const int lrow  = lane & 15;
    const int lcolh = (lane >> 4) << 3;

    auto ldfrag = [&](uint32_t st, int kc, int buf) {
#pragma unroll
        for (int mt = 0; mt < 2; mt++) {
            int r = wm * 32 + mt * 16 + lrow;
            uint32_t off = r * 128 + (kc * 16 + lcolh) * 2;
            off ^= ((off >> 3) & 0x70);
            ldsm_x4(ah[buf][mt], st + off);
            ldsm_x4(al[buf][mt], st + AL_OFF + off);
        }
#pragma unroll
        for (int np = 0; np < 2; np++) {
            int kr = kc * 16 + lrow;
            int c  = wn * 32 + np * 16 + lcolh;
            uint32_t off = kr * 128 + c * 2;
            off ^= ((off >> 3) & 0x70);
            ldsm_x4_t(bh[buf][np], st + BH_OFF + off);
            ldsm_x4_t(bl[buf][np], st + BL_OFF + off);
        }
    };

    auto mma_chunk = [&](int buf) {
#pragma unroll
        for (int mt = 0; mt < 2; mt++)
#pragma unroll
            for (int nt = 0; nt < 4; nt++) {
                const uint32_t* bhp = &bh[buf][nt >> 1][(nt & 1) * 2];
                const uint32_t* blp = &bl[buf][nt >> 1][(nt & 1) * 2];
                mma16816(acc[mt][nt], ah[buf][mt], bhp);
                mma16816(acc[mt][nt], ah[buf][mt], blp);
                mma16816(acc[mt][nt], al[buf][mt], bhp);
            }
    };

    const int T = K / BK;
    load_stage(0, 0);
    load_stage(1, 1);

    for (int t = 0; t < T; t++) {
        if (t < T - 1) CP_WAIT(1); else CP_WAIT(0);
        __syncthreads();
        if (t + 2 < T) load_stage(t + 2, (t + 2) % S);

        const uint32_t st = sbase + (t % S) * STAGE;
        ldfrag(st, 0, 0);
#pragma unroll
        for (int kc = 0; kc < 4; kc++) {
            if (kc < 3) ldfrag(st, kc + 1, (kc + 1) & 1);
            mma_chunk(kc & 1);
        }
        __syncthreads();
    }

    // epilogue
    const int rr0 = brow + wm * 32 + (lane >> 2);
    const int cc0 = bcol + wn * 32 + ((lane & 3) << 1);
    float aLv = 0.f, aHv = 0.f;
    if (EPI == 3) { aLv = aLp[0]; aHv = aHp[0]; }
#pragma unroll
    for (int mt = 0; mt < 2; mt++)
#pragma unroll
        for (int nt = 0; nt < 4; nt++) {
            int row = rr0 + mt * 16;
            int col = cc0 + nt * 8;
            float2 v0 = make_float2(acc[mt][nt][0], acc[mt][nt][1]);
            float2 v1 = make_float2(acc[mt][nt][2], acc[mt][nt][3]);
            if (EPI == 2) {
                v0.x = fmaxf(v0.x, 0.f); v0.y = fmaxf(v0.y, 0.f);
                v1.x = fmaxf(v1.x, 0.f); v1.y = fmaxf(v1.y, 0.f);
            }
            if (EPI == 0) {
                *(float2*)(Cf + (size_t)row * N + col)       = v0;
                *(float2*)(Cf + (size_t)(row + 8) * N + col) = v1;
            } else if (EPI == 3) {
                float2 b = *(const float2*)&bc[col];
#pragma unroll
                for (int sr = 0; sr < 2; sr++) {
                    int rw = row + sr * 8;
                    float ds = g_dis[rw];
                    float c2 = ds * ds;
                    float2 hl = *(const float2*)&g_Hl[(size_t)rw * N + col];
                    float2 xw = *(const float2*)&g_XW[(size_t)rw * N + col];
                    float2 v  = sr ? v1 : v0;
                    float2 r;
                    r.x = aLv * (hl.x + c2 * xw.x + b.x) + aHv * v.x;
                    r.y = aLv * (hl.y + c2 * xw.y + b.y) + aHv * v.y;
                    *(float2*)(Cf + (size_t)rw * N + col) = r;
                }
            } else {
                __nv_bfloat162 h0, l0, h1, l1;
                split2(v0.x, v0.y, h0, l0);
                split2(v1.x, v1.y, h1, l1);
                *(__nv_bfloat162*)(Ch + (size_t)row * N + col)       = h0;
                *(__nv_bfloat162*)(Cl + (size_t)row * N + col)       = l0;
                *(__nv_bfloat162*)(Ch + (size_t)(row + 8) * N + col) = h1;
                *(__nv_bfloat162*)(Cl + (size_t)(row + 8) * N + col) = l1;
            }
        }
}

// ---------------- GCN branch helpers ---------------------------------------
__global__ void zero_kernel()
{
    int gid = blockIdx.x * 256 + threadIdx.x;
    if (gid < NN * DIM) g_Hl[gid] = 0.0f;
    if (gid < NN)       g_deg[gid] = 0;
}

__global__ void detect_kernel(const int* __restrict__ ei32)
{
    if (blockIdx.x == 0 && threadIdx.x == 0) {
        int is64 = 1;
        for (int i = 0; i < 256; i++)
            if (ei32[2 * i + 1] != 0) { is64 = 0; break; }
        g_is64 = is64;
    }
}

__device__ __forceinline__ int edge_at(const void* ei, int pos, int is64)
{
    return is64 ? (int)((const long long*)ei)[pos] : ((const int*)ei)[pos];
}

__global__ void deg_kernel(const void* __restrict__ ei)
{
    int e = blockIdx.x * 256 + threadIdx.x;
    if (e >= NE) return;
    int d = edge_at(ei, NE + e, g_is64);
    atomicAdd(&g_deg[d], 1);
}

__global__ void dis_kernel()
{
    int n = blockIdx.x * 256 + threadIdx.x;
    if (n < NN) g_dis[n] = rsqrtf((float)(g_deg[n] + 1));
}

__global__ void scatter_kernel(const void* __restrict__ ei)
{
    int gid = blockIdx.x * 256 + threadIdx.x;
    int e = gid >> 6;
    if (e >= NE) return;
    int q = (gid & 63) << 2;
    int is64 = g_is64;
    int s = edge_at(ei, e, is64);
    int d = edge_at(ei, NE + e, is64);
    float coef = g_dis[s] * g_dis[d];
    float4 xw = *(const float4*)&g_XW[s * DIM + q];
    float4 m = make_float4(coef * xw.x, coef * xw.y, coef * xw.z, coef * xw.w);
    atomicAdd((float4*)&g_Hl[d * DIM + q], m);
}

// ---------------- launch ----------------------------------------------------
extern "C" void kernel_launch(void* const* d_in, const int* in_sizes, int n_in,
                              void* d_out, int out_size)
{
    const float* x    = (const float*)d_in[0];
    const void*  ei   = d_in[1];
    const float* lap  = (const float*)d_in[2];
    const float* dinv = (const float*)d_in[3];
    const float* Wh   = (const float*)d_in[4];
    const float* Wc   = (const float*)d_in[5];
    const float* bc   = (const float*)d_in[6];
    const float* aL   = (const float*)d_in[7];
    const float* aH   = (const float*)d_in[8];
    float* out = (float*)d_out;

    __nv_bfloat16 *lapH, *lapL, *dH, *dL, *xH, *xL, *WhH, *WhL, *WcH, *WcL;
    __nv_bfloat16 *T0H, *T0L, *T1H, *T1L, *T2H, *T2L;
    float *XW;
    cudaGetSymbolAddress((void**)&lapH, g_lapH); cudaGetSymbolAddress((void**)&lapL, g_lapL);
    cudaGetSymbolAddress((void**)&dH,   g_dH);   cudaGetSymbolAddress((void**)&dL,   g_dL);
    cudaGetSymbolAddress((void**)&xH,   g_xH);   cudaGetSymbolAddress((void**)&xL,   g_xL);
    cudaGetSymbolAddress((void**)&WhH,  g_WhH);  cudaGetSymbolAddress((void**)&WhL,  g_WhL);
    cudaGetSymbolAddress((void**)&WcH,  g_WcH);  cudaGetSymbolAddress((void**)&WcL,  g_WcL);
    cudaGetSymbolAddress((void**)&T0H,  g_T0H);  cudaGetSymbolAddress((void**)&T0L,  g_T0L);
    cudaGetSymbolAddress((void**)&T1H,  g_T1H);  cudaGetSymbolAddress((void**)&T1L,  g_T1L);
    cudaGetSymbolAddress((void**)&T2H,  g_T2H);  cudaGetSymbolAddress((void**)&T2L,  g_T2L);
    cudaGetSymbolAddress((void**)&XW,   g_XW);

    constexpr int SMEM_BYTES = 3 * 49152;   // 144 KB dynamic smem

    static cudaStream_t side = nullptr;
    static cudaEvent_t evFork, evE1, evE2, evE3;
    if (!side) {
        cudaFuncSetAttribute(gemm_mm<0>, cudaFuncAttributeMaxDynamicSharedMemorySize, SMEM_BYTES);
        cudaFuncSetAttribute(gemm_mm<1>, cudaFuncAttributeMaxDynamicSharedMemorySize, SMEM_BYTES);
        cudaFuncSetAttribute(gemm_mm<2>, cudaFuncAttributeMaxDynamicSharedMemorySize, SMEM_BYTES);
        cudaFuncSetAttribute(gemm_mm<3>, cudaFuncAttributeMaxDynamicSharedMemorySize, SMEM_BYTES);
        cudaStreamCreateWithFlags(&side, cudaStreamNonBlocking);
        cudaEventCreateWithFlags(&evFork, cudaEventDisableTiming);
        cudaEventCreateWithFlags(&evE1,   cudaEventDisableTiming);
        cudaEventCreateWithFlags(&evE2,   cudaEventDisableTiming);
        cudaEventCreateWithFlags(&evE3,   cudaEventDisableTiming);
    }

    const dim3 gridG(DIM / 64, NN / 128);   // 4 x 32 = 128 CTAs

    // ---- main stream: detect, then fork ----
    detect_kernel<<<1, 32>>>((const int*)ei);
    cudaEventRecord(evFork, 0);
    cudaStreamWaitEvent(side, evFork, 0);

    // ---- side stream: lap split (needed by G2) ----
    split_mat<<<(NN * NN / 4) / 256, 256, 0, side>>>((const float4*)lap, (uint2*)lapH, (uint2*)lapL, NN * NN / 4);
    cudaEventRecord(evE2, side);

    // ---- main: x split (E1), dinv split, Wh split, T0 ----
    split_mat<<<(NN * DIM / 4) / 256, 256>>>((const float4*)x, (uint2*)xH, (uint2*)xL, NN * DIM / 4);
    cudaEventRecord(evE1, 0);
    split_mat<<<(NN * NN / 4) / 256, 256>>>((const float4*)dinv, (uint2*)dH, (uint2*)dL, NN * NN / 4);
    split_mat<<<(DIM * DIM / 4 + 255) / 256, 256>>>((const float4*)Wh, (uint2*)WhH, (uint2*)WhL, DIM * DIM / 4);
    gemm_mm<2><<<gridG, 256, SMEM_BYTES>>>(xH, xL, WhH, WhL, DIM, nullptr, T0H, T0L,
                                           nullptr, nullptr, nullptr);

    // ---- side: GCN branch (Wc split, zero, XW, deg, dis, scatter) ----
    split_mat<<<(DIM * DIM / 4 + 255) / 256, 256, 0, side>>>((const float4*)Wc, (uint2*)WcH, (uint2*)WcL, DIM * DIM / 4);
    zero_kernel<<<(NN * DIM) / 256, 256, 0, side>>>();
    cudaStreamWaitEvent(side, evE1, 0);     // XW needs x split
    gemm_mm<0><<<gridG, 256, SMEM_BYTES, side>>>(xH, xL, WcH, WcL, DIM, XW, nullptr, nullptr,
                                                 nullptr, nullptr, nullptr);
    deg_kernel<<<NE / 256, 256, 0, side>>>(ei);
    dis_kernel<<<NN / 256, 256, 0, side>>>();
    scatter_kernel<<<(NE * 64) / 256, 256, 0, side>>>(ei);
    cudaEventRecord(evE3, side);

    // ---- main: high-pass chain ----
    gemm_mm<1><<<gridG, 256, SMEM_BYTES>>>(dH, dL, T0H, T0L, NN, nullptr, T1H, T1L,
                                           nullptr, nullptr, nullptr);
    cudaStreamWaitEvent(0, evE2, 0);        // lap split done
    gemm_mm<1><<<gridG, 256, SMEM_BYTES>>>(lapH, lapL, T1H, T1L, NN, nullptr, T2H, T2L,
                                           nullptr, nullptr, nullptr);
    cudaStreamWaitEvent(0, evE3, 0);        // scatter branch done
    // G3 with fused combine: out = aL*(Hl + dis^2*XW + bc) + aH*(dinv @ T2)
    gemm_mm<3><<<gridG, 256, SMEM_BYTES>>>(dH, dL, T2H, T2L, NN, out, nullptr, nullptr,
                                           bc, aL, aH);
}

// round 13
// speedup vs baseline: 3.0688x; 1.0855x over previous
#include <cuda_runtime.h>
#include <cuda_bf16.h>
#include <cstdint>

#define NN   4096
#define DIM  256
#define NE   131072

// ---------------- scratch (device globals: no allocation allowed) ----------
__device__ __nv_bfloat16 g_lapH[NN * NN], g_lapL[NN * NN];
__device__ __nv_bfloat16 g_dH[NN * NN],   g_dL[NN * NN];
__device__ __nv_bfloat16 g_xH[NN * DIM],  g_xL[NN * DIM];
__device__ __nv_bfloat16 g_WhH[DIM * DIM], g_WhL[DIM * DIM];
__device__ __nv_bfloat16 g_WcH[DIM * DIM], g_WcL[DIM * DIM];
__device__ __nv_bfloat16 g_T0H[NN * DIM], g_T0L[NN * DIM];
__device__ __nv_bfloat16 g_T1H[NN * DIM], g_T1L[NN * DIM];
__device__ __nv_bfloat16 g_T2H[NN * DIM], g_T2L[NN * DIM];
__device__ float g_XW[NN * DIM];
__device__ float g_Hl[NN * DIM];
__device__ int   g_deg[NN];
__device__ float g_dis[NN];
__device__ int   g_is64;

// ---------------- PTX helpers -----------------------------------------------
__device__ __forceinline__ uint32_t smem_u32(const void* p)
{
    uint32_t a;
    asm("{ .reg .u64 t; cvta.to.shared.u64 t, %1; cvt.u32.u64 %0, t; }"
        : "=r"(a) : "l"(p));
    return a;
}
__device__ __forceinline__ void ldsm_x4(uint32_t* r, uint32_t a)
{
    asm volatile("ldmatrix.sync.aligned.m8n8.x4.shared.b16 {%0,%1,%2,%3},[%4];"
                 : "=r"(r[0]), "=r"(r[1]), "=r"(r[2]), "=r"(r[3]) : "r"(a));
}
__device__ __forceinline__ void ldsm_x4_t(uint32_t* r, uint32_t a)
{
    asm volatile("ldmatrix.sync.aligned.m8n8.x4.trans.shared.b16 {%0,%1,%2,%3},[%4];"
                 : "=r"(r[0]), "=r"(r[1]), "=r"(r[2]), "=r"(r[3]) : "r"(a));
}
__device__ __forceinline__ void mma16816(float* c, const uint32_t* a, const uint32_t* b)
{
    asm volatile(
        "mma.sync.aligned.m16n8k16.row.col.f32.bf16.bf16.f32 "
        "{%0,%1,%2,%3},{%4,%5,%6,%7},{%8,%9},{%0,%1,%2,%3};"
        : "+f"(c[0]), "+f"(c[1]), "+f"(c[2]), "+f"(c[3])
        : "r"(a[0]), "r"(a[1]), "r"(a[2]), "r"(a[3]), "r"(b[0]), "r"(b[1]));
}
__device__ __forceinline__ void cpa16(uint32_t smem, const void* gmem)
{
    asm volatile("cp.async.cg.shared.global [%0],[%1],16;" :: "r"(smem), "l"(gmem));
}
#define CP_COMMIT() asm volatile("cp.async.commit_group;")
#define CP_WAIT(n)  asm volatile("cp.async.wait_group %0;" :: "n"(n))

// split fp32 -> (hi, lo) bf16
__device__ __forceinline__ void split1(float v, __nv_bfloat16& h, __nv_bfloat16& l)
{
    h = __float2bfloat16_rn(v);
    l = __float2bfloat16_rn(v - __bfloat162float(h));
}
__device__ __forceinline__ void split2(float x, float y,
                                       __nv_bfloat162& hp, __nv_bfloat162& lp)
{
    split1(x, hp.x, lp.x);
    split1(y, hp.y, lp.y);
}

// ---------------- conversion kernel -----------------------------------------
__global__ void split_mat(const float4* __restrict__ src,
                          uint2* __restrict__ h, uint2* __restrict__ l, int n4)
{
    int i = blockIdx.x * 256 + threadIdx.x;
    if (i >= n4) return;
    float4 v = src[i];
    __nv_bfloat162 h0, l0, h1, l1;
    split2(v.x, v.y, h0, l0);
    split2(v.z, v.w, h1, l1);
    h[i] = make_uint2(reinterpret_cast<uint32_t&>(h0), reinterpret_cast<uint32_t&>(h1));
    l[i] = make_uint2(reinterpret_cast<uint32_t&>(l0), reinterpret_cast<uint32_t&>(l1));
}

// ---------------- bf16x3 mma.sync GEMM, K-split 2 groups, warp tile 64x32 ---
// C[M,256] = A[M,K] @ B[K,256]; A/B pre-split bf16 hi/lo, natural layouts.
// acc += Ah*Bh + Ah*Bl + Al*Bh. BM=128, BN=64, BK=64, 256 threads.
// 8 warps = 2 K-groups x 4 warps (2(M) x 2(N), warp tile 64x32).
// Group g processes K-tiles with t%2==g; cross-group fp32 reduce via smem.
// S=4 stages, one wait+2 barriers per PAIR of tiles.
// EPI: 0 = fp32 out; 1 = bf16 hi/lo out; 2 = relu + bf16 hi/lo out;
//      3 = fused FBGCN combine: out = aL*(Hl + dis^2*XW + bc) + aH*acc.
template <int EPI>
__global__ __launch_bounds__(256)
void gemm_mm(const __nv_bfloat16* __restrict__ Ah, const __nv_bfloat16* __restrict__ Al,
             const __nv_bfloat16* __restrict__ Bh, const __nv_bfloat16* __restrict__ Bl,
             int K, float* __restrict__ Cf,
             __nv_bfloat16* __restrict__ Ch, __nv_bfloat16* __restrict__ Cl,
             const float* __restrict__ bc, const float* __restrict__ aLp,
             const float* __restrict__ aHp)
{
    constexpr int BM = 128, BN = 64, BK = 64, N = 256, S = 4;
    constexpr int AL_OFF = 16384;          // A: 128 rows x 128B
    constexpr int BH_OFF = 32768;          // B: 64 k-rows x 128B
    constexpr int BL_OFF = 40960;
    constexpr int STAGE  = 49152;          // 48 KB per stage

    extern __shared__ __align__(1024) char dsm[];
    const uint32_t sbase = smem_u32(dsm);

    const int tid  = threadIdx.x;
    const int lane = tid & 31;
    const int wid  = tid >> 5;
    const int grp  = wid >> 2;             // K-group 0/1
    const int wg   = wid & 3;              // warp within group
    const int wm   = wg >> 1;              // 0..1 -> rows wm*64
    const int wn   = wg & 1;               // 0..1 -> cols wn*32
    const int brow = blockIdx.y * BM;
    const int bcol = blockIdx.x * BN;

    // cp.async mapping (all 256 threads load every tile)
    const int r0   = tid >> 3;
    const int cb   = (tid & 7) * 16;
    const int kkel = (tid & 7) * 8;

    auto load_stage = [&](int tk) {
        const uint32_t st = sbase + (tk & 3) * STAGE;
        const int k0 = tk * BK;
#pragma unroll
        for (int i = 0; i < 4; i++) {
            int row = r0 + 32 * i;
            uint32_t off = row * 128 + cb;
            off ^= ((off >> 3) & 0x70);
            const size_t g = (size_t)(brow + row) * K + k0 + kkel;
            cpa16(st + off,          Ah + g);
            cpa16(st + AL_OFF + off, Al + g);
        }
#pragma unroll
        for (int i = 0; i < 2; i++) {
            int kr = r0 + 32 * i;
            uint32_t off = kr * 128 + cb;
            off ^= ((off >> 3) & 0x70);
            const size_t g = (size_t)(k0 + kr) * N + bcol + kkel;
            cpa16(st + BH_OFF + off, Bh + g);
            cpa16(st + BL_OFF + off, Bl + g);
        }
        CP_COMMIT();
    };

    float acc[4][4][4];
#pragma unroll
    for (int i = 0; i < 4; i++)
#pragma unroll
        for (int j = 0; j < 4; j++)
#pragma unroll
            for (int q = 0; q < 4; q++) acc[i][j][q] = 0.0f;

    uint32_t ah[2][4][4], al[2][4][4], bh[2][2][4], bl[2][2][4];
    const int lrow  = lane & 15;
    const int lcolh = (lane >> 4) << 3;

    auto ldfrag = [&](uint32_t st, int kc, int buf) {
#pragma unroll
        for (int mt = 0; mt < 4; mt++) {
            int r = wm * 64 + mt * 16 + lrow;
            uint32_t off = r * 128 + (kc * 16 + lcolh) * 2;
            off ^= ((off >> 3) & 0x70);
            ldsm_x4(ah[buf][mt], st + off);
            ldsm_x4(al[buf][mt], st + AL_OFF + off);
        }
#pragma unroll
        for (int np = 0; np < 2; np++) {
            int kr = kc * 16 + lrow;
            int c  = wn * 32 + np * 16 + lcolh;
            uint32_t off = kr * 128 + c * 2;
            off ^= ((off >> 3) & 0x70);
            ldsm_x4_t(bh[buf][np], st + BH_OFF + off);
            ldsm_x4_t(bl[buf][np], st + BL_OFF + off);
        }
    };

    auto mma_chunk = [&](int buf) {
#pragma unroll
        for (int mt = 0; mt < 4; mt++)
#pragma unroll
            for (int nt = 0; nt < 4; nt++) {
                const uint32_t* bhp = &bh[buf][nt >> 1][(nt & 1) * 2];
                const uint32_t* blp = &bl[buf][nt >> 1][(nt & 1) * 2];
                mma16816(acc[mt][nt], ah[buf][mt], bhp);
                mma16816(acc[mt][nt], ah[buf][mt], blp);
                mma16816(acc[mt][nt], al[buf][mt], bhp);
            }
    };

    const int T = K / BK;                  // multiple of 4 (K = 256 or 4096)
    const int npairs = T / 2;
    load_stage(0); load_stage(1); load_stage(2); load_stage(3);

    for (int i = 0; i < npairs; i++) {
        if (i < npairs - 1) CP_WAIT(2); else CP_WAIT(0);
        __syncthreads();

        const int mytile = 2 * i + grp;
        const uint32_t st = sbase + (mytile & 3) * STAGE;
        ldfrag(st, 0, 0);
#pragma unroll
        for (int kc = 0; kc < 4; kc++) {
            if (kc < 3) ldfrag(st, kc + 1, (kc + 1) & 1);
            mma_chunk(kc & 1);
        }
        __syncthreads();
        if (2 * i + 4 < T) { load_stage(2 * i + 4); load_stage(2 * i + 5); }
    }

    // ---- cross-group reduction: group 1 dumps, group 0 adds ----
    // lane-interleaved layout: elem j of lane l of warp wg at [wg*2048 + j*32 + l]
    float* red = (float*)dsm;              // 4 warps x 8 KB = 32 KB (stage 0 reuse)
    if (grp == 1) {
#pragma unroll
        for (int mt = 0; mt < 4; mt++)
#pragma unroll
            for (int nt = 0; nt < 4; nt++)
#pragma unroll
                for (int q = 0; q < 4; q++)
                    red[wg * 2048 + (mt * 16 + nt * 4 + q) * 32 + lane] = acc[mt][nt][q];
    }
    __syncthreads();
    if (grp == 1) return;
#pragma unroll
    for (int mt = 0; mt < 4; mt++)
#pragma unroll
        for (int nt = 0; nt < 4; nt++)
#pragma unroll
            for (int q = 0; q < 4; q++)
                acc[mt][nt][q] += red[wg * 2048 + (mt * 16 + nt * 4 + q) * 32 + lane];

    // ---- epilogue (group 0 only; full 128x64 tile covered) ----
    const int rr0 = brow + wm * 64 + (lane >> 2);
    const int cc0 = bcol + wn * 32 + ((lane & 3) << 1);
    float aLv = 0.f, aHv = 0.f;
    if (EPI == 3) { aLv = aLp[0]; aHv = aHp[0]; }
#pragma unroll
    for (int mt = 0; mt < 4; mt++)
#pragma unroll
        for (int nt = 0; nt < 4; nt++) {
            int row = rr0 + mt * 16;
            int col = cc0 + nt * 8;
            float2 v0 = make_float2(acc[mt][nt][0], acc[mt][nt][1]);
            float2 v1 = make_float2(acc[mt][nt][2], acc[mt][nt][3]);
            if (EPI == 2) {
                v0.x = fmaxf(v0.x, 0.f); v0.y = fmaxf(v0.y, 0.f);
                v1.x = fmaxf(v1.x, 0.f); v1.y = fmaxf(v1.y, 0.f);
            }
            if (EPI == 0) {
                *(float2*)(Cf + (size_t)row * N + col)       = v0;
                *(float2*)(Cf + (size_t)(row + 8) * N + col) = v1;
            } else if (EPI == 3) {
                float2 b = *(const float2*)&bc[col];
#pragma unroll
                for (int sr = 0; sr < 2; sr++) {
                    int rw = row + sr * 8;
                    float ds = g_dis[rw];
                    float c2 = ds * ds;
                    float2 hl = *(const float2*)&g_Hl[(size_t)rw * N + col];
                    float2 xw = *(const float2*)&g_XW[(size_t)rw * N + col];
                    float2 v  = sr ? v1 : v0;
                    float2 r;
                    r.x = aLv * (hl.x + c2 * xw.x + b.x) + aHv * v.x;
                    r.y = aLv * (hl.y + c2 * xw.y + b.y) + aHv * v.y;
                    *(float2*)(Cf + (size_t)rw * N + col) = r;
                }
            } else {
                __nv_bfloat162 h0, l0, h1, l1;
                split2(v0.x, v0.y, h0, l0);
                split2(v1.x, v1.y, h1, l1);
                *(__nv_bfloat162*)(Ch + (size_t)row * N + col)       = h0;
                *(__nv_bfloat162*)(Cl + (size_t)row * N + col)       = l0;
                *(__nv_bfloat162*)(Ch + (size_t)(row + 8) * N + col) = h1;
                *(__nv_bfloat162*)(Cl + (size_t)(row + 8) * N + col) = l1;
            }
        }
}

// ---------------- GCN branch helpers ---------------------------------------
__global__ void zero_kernel()
{
    int gid = blockIdx.x * 256 + threadIdx.x;
    if (gid < NN * DIM) g_Hl[gid] = 0.0f;
    if (gid < NN)       g_deg[gid] = 0;
}

__global__ void detect_kernel(const int* __restrict__ ei32)
{
    if (blockIdx.x == 0 && threadIdx.x == 0) {
        int is64 = 1;
        for (int i = 0; i < 256; i++)
            if (ei32[2 * i + 1] != 0) { is64 = 0; break; }
        g_is64 = is64;
    }
}

__device__ __forceinline__ int edge_at(const void* ei, int pos, int is64)
{
    return is64 ? (int)((const long long*)ei)[pos] : ((const int*)ei)[pos];
}

__global__ void deg_kernel(const void* __restrict__ ei)
{
    int e = blockIdx.x * 256 + threadIdx.x;
    if (e >= NE) return;
    int d = edge_at(ei, NE + e, g_is64);
    atomicAdd(&g_deg[d], 1);
}

__global__ void dis_kernel()
{
    int n = blockIdx.x * 256 + threadIdx.x;
    if (n < NN) g_dis[n] = rsqrtf((float)(g_deg[n] + 1));
}

__global__ void scatter_kernel(const void* __restrict__ ei)
{
    int gid = blockIdx.x * 256 + threadIdx.x;
    int e = gid >> 6;
    if (e >= NE) return;
    int q = (gid & 63) << 2;
    int is64 = g_is64;
    int s = edge_at(ei, e, is64);
    int d = edge_at(ei, NE + e, is64);
    float coef = g_dis[s] * g_dis[d];
    float4 xw = *(const float4*)&g_XW[s * DIM + q];
    float4 m = make_float4(coef * xw.x, coef * xw.y, coef * xw.z, coef * xw.w);
    atomicAdd((float4*)&g_Hl[d * DIM + q], m);
}

// ---------------- launch ----------------------------------------------------
extern "C" void kernel_launch(void* const* d_in, const int* in_sizes, int n_in,
                              void* d_out, int out_size)
{
    const float* x    = (const float*)d_in[0];
    const void*  ei   = d_in[1];
    const float* lap  = (const float*)d_in[2];
    const float* dinv = (const float*)d_in[3];
    const float* Wh   = (const float*)d_in[4];
    const float* Wc   = (const float*)d_in[5];
    const float* bc   = (const float*)d_in[6];
    const float* aL   = (const float*)d_in[7];
    const float* aH   = (const float*)d_in[8];
    float* out = (float*)d_out;

    __nv_bfloat16 *lapH, *lapL, *dH, *dL, *xH, *xL, *WhH, *WhL, *WcH, *WcL;
    __nv_bfloat16 *T0H, *T0L, *T1H, *T1L, *T2H, *T2L;
    float *XW;
    cudaGetSymbolAddress((void**)&lapH, g_lapH); cudaGetSymbolAddress((void**)&lapL, g_lapL);
    cudaGetSymbolAddress((void**)&dH,   g_dH);   cudaGetSymbolAddress((void**)&dL,   g_dL);
    cudaGetSymbolAddress((void**)&xH,   g_xH);   cudaGetSymbolAddress((void**)&xL,   g_xL);
    cudaGetSymbolAddress((void**)&WhH,  g_WhH);  cudaGetSymbolAddress((void**)&WhL,  g_WhL);
    cudaGetSymbolAddress((void**)&WcH,  g_WcH);  cudaGetSymbolAddress((void**)&WcL,  g_WcL);
    cudaGetSymbolAddress((void**)&T0H,  g_T0H);  cudaGetSymbolAddress((void**)&T0L,  g_T0L);
    cudaGetSymbolAddress((void**)&T1H,  g_T1H);  cudaGetSymbolAddress((void**)&T1L,  g_T1L);
    cudaGetSymbolAddress((void**)&T2H,  g_T2H);  cudaGetSymbolAddress((void**)&T2L,  g_T2L);
    cudaGetSymbolAddress((void**)&XW,   g_XW);

    constexpr int SMEM_BYTES = 4 * 49152;   // 192 KB dynamic smem

    static cudaStream_t side = nullptr;
    static cudaEvent_t evFork, evE1, evE2, evE3;
    if (!side) {
        cudaFuncSetAttribute(gemm_mm<0>, cudaFuncAttributeMaxDynamicSharedMemorySize, SMEM_BYTES);
        cudaFuncSetAttribute(gemm_mm<1>, cudaFuncAttributeMaxDynamicSharedMemorySize, SMEM_BYTES);
        cudaFuncSetAttribute(gemm_mm<2>, cudaFuncAttributeMaxDynamicSharedMemorySize, SMEM_BYTES);
        cudaFuncSetAttribute(gemm_mm<3>, cudaFuncAttributeMaxDynamicSharedMemorySize, SMEM_BYTES);
        cudaStreamCreateWithFlags(&side, cudaStreamNonBlocking);
        cudaEventCreateWithFlags(&evFork, cudaEventDisableTiming);
        cudaEventCreateWithFlags(&evE1,   cudaEventDisableTiming);
        cudaEventCreateWithFlags(&evE2,   cudaEventDisableTiming);
        cudaEventCreateWithFlags(&evE3,   cudaEventDisableTiming);
    }

    const dim3 gridG(DIM / 64, NN / 128);   // 4 x 32 = 128 CTAs

    // ---- main stream: detect, then fork ----
    detect_kernel<<<1, 32>>>((const int*)ei);
    cudaEventRecord(evFork, 0);
    cudaStreamWaitEvent(side, evFork, 0);

    // ---- side stream: lap split (needed by G2) ----
    split_mat<<<(NN * NN / 4) / 256, 256, 0, side>>>((const float4*)lap, (uint2*)lapH, (uint2*)lapL, NN * NN / 4);
    cudaEventRecord(evE2, side);

    // ---- main: x split (E1), dinv split, Wh split, T0 ----
    split_mat<<<(NN * DIM / 4) / 256, 256>>>((const float4*)x, (uint2*)xH, (uint2*)xL, NN * DIM / 4);
    cudaEventRecord(evE1, 0);
    split_mat<<<(NN * NN / 4) / 256, 256>>>((const float4*)dinv, (uint2*)dH, (uint2*)dL, NN * NN / 4);
    split_mat<<<(DIM * DIM / 4 + 255) / 256, 256>>>((const float4*)Wh, (uint2*)WhH, (uint2*)WhL, DIM * DIM / 4);
    gemm_mm<2><<<gridG, 256, SMEM_BYTES>>>(xH, xL, WhH, WhL, DIM, nullptr, T0H, T0L,
                                           nullptr, nullptr, nullptr);

    // ---- side: GCN branch (Wc split, zero, XW, deg, dis, scatter) ----
    split_mat<<<(DIM * DIM / 4 + 255) / 256, 256, 0, side>>>((const float4*)Wc, (uint2*)WcH, (uint2*)WcL, DIM * DIM / 4);
    zero_kernel<<<(NN * DIM) / 256, 256, 0, side>>>();
    cudaStreamWaitEvent(side, evE1, 0);     // XW needs x split
    gemm_mm<0><<<gridG, 256, SMEM_BYTES, side>>>(xH, xL, WcH, WcL, DIM, XW, nullptr, nullptr,
                                                 nullptr, nullptr, nullptr);
    deg_kernel<<<NE / 256, 256, 0, side>>>(ei);
    dis_kernel<<<NN / 256, 256, 0, side>>>();
    scatter_kernel<<<(NE * 64) / 256, 256, 0, side>>>(ei);
    cudaEventRecord(evE3, side);

    // ---- main: high-pass chain ----
    gemm_mm<1><<<gridG, 256, SMEM_BYTES>>>(dH, dL, T0H, T0L, NN, nullptr, T1H, T1L,
                                           nullptr, nullptr, nullptr);
    cudaStreamWaitEvent(0, evE2, 0);        // lap split done
    gemm_mm<1><<<gridG, 256, SMEM_BYTES>>>(lapH, lapL, T1H, T1L, NN, nullptr, T2H, T2L,
                                           nullptr, nullptr, nullptr);
    cudaStreamWaitEvent(0, evE3, 0);        // scatter branch done
    // G3 with fused combine: out = aL*(Hl + dis^2*XW + bc) + aH*(dinv @ T2)
    gemm_mm<3><<<gridG, 256, SMEM_BYTES>>>(dH, dL, T2H, T2L, NN, out, nullptr, nullptr,
                                           bc, aL, aH);
}

// round 15
// speedup vs baseline: 3.2426x; 1.0566x over previous
#include <cuda_runtime.h>
#include <cuda_bf16.h>
#include <cstdint>

#define NN   4096
#define DIM  256
#define NE   131072

// ---------------- scratch (device globals: no allocation allowed) ----------
__device__ __nv_bfloat16 g_lapH[NN * NN], g_lapL[NN * NN];
__device__ __nv_bfloat16 g_dH[NN * NN],   g_dL[NN * NN];
__device__ __nv_bfloat16 g_xH[NN * DIM],  g_xL[NN * DIM];
__device__ __nv_bfloat16 g_WhH[DIM * DIM], g_WhL[DIM * DIM];
__device__ __nv_bfloat16 g_WcH[DIM * DIM], g_WcL[DIM * DIM];
__device__ __nv_bfloat16 g_T0H[NN * DIM], g_T0L[NN * DIM];
__device__ __nv_bfloat16 g_T1H[NN * DIM], g_T1L[NN * DIM];
__device__ __nv_bfloat16 g_T2H[NN * DIM], g_T2L[NN * DIM];
__device__ float g_XW[NN * DIM];
__device__ float g_Hl[NN * DIM];
__device__ int   g_deg[NN];
__device__ float g_dis[NN];
__device__ int   g_is64;

// ---------------- PTX helpers -----------------------------------------------
__device__ __forceinline__ uint32_t smem_u32(const void* p)
{
    uint32_t a;
    asm("{ .reg .u64 t; cvta.to.shared.u64 t, %1; cvt.u32.u64 %0, t; }"
        : "=r"(a) : "l"(p));
    return a;
}
__device__ __forceinline__ void ldsm_x4(uint32_t* r, uint32_t a)
{
    asm volatile("ldmatrix.sync.aligned.m8n8.x4.shared.b16 {%0,%1,%2,%3},[%4];"
                 : "=r"(r[0]), "=r"(r[1]), "=r"(r[2]), "=r"(r[3]) : "r"(a));
}
__device__ __forceinline__ void ldsm_x4_t(uint32_t* r, uint32_t a)
{
    asm volatile("ldmatrix.sync.aligned.m8n8.x4.trans.shared.b16 {%0,%1,%2,%3},[%4];"
                 : "=r"(r[0]), "=r"(r[1]), "=r"(r[2]), "=r"(r[3]) : "r"(a));
}
__device__ __forceinline__ void mma16816(float* c, const uint32_t* a, const uint32_t* b)
{
    asm volatile(
        "mma.sync.aligned.m16n8k16.row.col.f32.bf16.bf16.f32 "
        "{%0,%1,%2,%3},{%4,%5,%6,%7},{%8,%9},{%0,%1,%2,%3};"
        : "+f"(c[0]), "+f"(c[1]), "+f"(c[2]), "+f"(c[3])
        : "r"(a[0]), "r"(a[1]), "r"(a[2]), "r"(a[3]), "r"(b[0]), "r"(b[1]));
}
__device__ __forceinline__ void cpa16(uint32_t smem, const void* gmem)
{
    asm volatile("cp.async.cg.shared.global [%0],[%1],16;" :: "r"(smem), "l"(gmem));
}
#define CP_COMMIT() asm volatile("cp.async.commit_group;")
#define CP_WAIT(n)  asm volatile("cp.async.wait_group %0;" :: "n"(n))
#define BAR_GRP(id) asm volatile("bar.sync %0, 128;" :: "r"(id) : "memory")

// split fp32 -> (hi, lo) bf16
__device__ __forceinline__ void split1(float v, __nv_bfloat16& h, __nv_bfloat16& l)
{
    h = __float2bfloat16_rn(v);
    l = __float2bfloat16_rn(v - __bfloat162float(h));
}
__device__ __forceinline__ void split2(float x, float y,
                                       __nv_bfloat162& hp, __nv_bfloat162& lp)
{
    split1(x, hp.x, lp.x);
    split1(y, hp.y, lp.y);
}

// ---------------- conversion kernels ----------------------------------------
__global__ void split_mat(const float4* __restrict__ src,
                          uint2* __restrict__ h, uint2* __restrict__ l, int n4)
{
    int i = blockIdx.x * 256 + threadIdx.x;
    if (i >= n4) return;
    float4 v = src[i];
    __nv_bfloat162 h0, l0, h1, l1;
    split2(v.x, v.y, h0, l0);
    split2(v.z, v.w, h1, l1);
    h[i] = make_uint2(reinterpret_cast<uint32_t&>(h0), reinterpret_cast<uint32_t&>(h1));
    l[i] = make_uint2(reinterpret_cast<uint32_t&>(l0), reinterpret_cast<uint32_t&>(l1));
}

// fused split of x (1024 blocks), Wh (64), Wc (64)
__global__ void split3(const float4* __restrict__ x,  uint2* __restrict__ xh, uint2* __restrict__ xl,
                       const float4* __restrict__ wh, uint2* __restrict__ whh, uint2* __restrict__ whl,
                       const float4* __restrict__ wc, uint2* __restrict__ wch, uint2* __restrict__ wcl)
{
    int b = blockIdx.x;
    const float4* src; uint2 *h, *l; int i;
    if (b < 1024)      { src = x;  h = xh;  l = xl;  i = b * 256 + threadIdx.x; }
    else if (b < 1088) { src = wh; h = whh; l = whl; i = (b - 1024) * 256 + threadIdx.x; }
    else               { src = wc; h = wch; l = wcl; i = (b - 1088) * 256 + threadIdx.x; }
    float4 v = src[i];
    __nv_bfloat162 h0, l0, h1, l1;
    split2(v.x, v.y, h0, l0);
    split2(v.z, v.w, h1, l1);
    h[i] = make_uint2(reinterpret_cast<uint32_t&>(h0), reinterpret_cast<uint32_t&>(h1));
    l[i] = make_uint2(reinterpret_cast<uint32_t&>(l0), reinterpret_cast<uint32_t&>(l1));
}

// ---------------- bf16x3 mma.sync GEMM, 2 decoupled K-groups ---------------
// C[M,256] = A[M,K] @ B[K,256]; pre-split bf16 hi/lo, natural layouts.
// acc += Ah*Bh + Ah*Bl + Al*Bh. BM=128, BN=64, BK=64, 256 threads.
// 8 warps = 2 K-groups x 4 warps (warp tile 64x32). Group g owns K-tiles
// t%2==g and smem stages {g, g+2}; loads its own stages; syncs with named
// barrier (g+1) only -> groups never block each other in the mainloop.
// EPI: 0 fp32 | 1 bf16 hi/lo | 2 relu+hi/lo | 3 fused FBGCN combine |
//      4 z-dispatch: z==0 relu+hi/lo (B=Bh/Bl), z==1 fp32->Cf (B=B2h/B2l).
template <int EPI>
__global__ __launch_bounds__(256)
void gemm_mm(const __nv_bfloat16* __restrict__ Ah, const __nv_bfloat16* __restrict__ Al,
             const __nv_bfloat16* Bh, const __nv_bfloat16* Bl,
             int K, float* __restrict__ Cf,
             __nv_bfloat16* __restrict__ Ch, __nv_bfloat16* __restrict__ Cl,
             const float* __restrict__ bc, const float* __restrict__ aLp,
             const float* __restrict__ aHp,
             const __nv_bfloat16* B2h, const __nv_bfloat16* B2l)
{
    constexpr int BM = 128, BN = 64, BK = 64, N = 256;
    constexpr int AL_OFF = 16384;
    constexpr int BH_OFF = 32768;
    constexpr int BL_OFF = 40960;
    constexpr int STAGE  = 49152;          // 48 KB per stage, 4 stages

    if (EPI == 4 && blockIdx.z == 1) { Bh = B2h; Bl = B2l; }

    extern __shared__ __align__(1024) char dsm[];
    const uint32_t sbase = smem_u32(dsm);

    const int tid  = threadIdx.x;
    const int lane = tid & 31;
    const int wid  = tid >> 5;
    const int grp  = wid >> 2;             // K-group 0/1
    const int wg   = wid & 3;
    const int wm   = wg >> 1;
    const int wn   = wg & 1;
    const int gtid = tid & 127;
    const int brow = blockIdx.y * BM;
    const int bcol = blockIdx.x * BN;

    // per-group load: 128 threads fill one 48 KB stage (24 cp.async each)
    auto load_stage = [&](int tk) {
        const uint32_t st = sbase + (tk & 3) * STAGE;
        const int k0 = tk * BK;
#pragma unroll
        for (int i = 0; i < 8; i++) {      // Ah/Al: 1024 16B chunks each
            int c = gtid + 128 * i;
            int row = c >> 3;
            uint32_t off = row * 128 + (c & 7) * 16;
            off ^= ((off >> 3) & 0x70);
            const size_t g = (size_t)(brow + row) * K + k0 + (c & 7) * 8;
            cpa16(st + off,          Ah + g);
            cpa16(st + AL_OFF + off, Al + g);
        }
#pragma unroll
        for (int i = 0; i < 4; i++) {      // Bh/Bl: 512 chunks each
            int c = gtid + 128 * i;
            int kr = c >> 3;
            uint32_t off = kr * 128 + (c & 7) * 16;
            off ^= ((off >> 3) & 0x70);
            const size_t g = (size_t)(k0 + kr) * N + bcol + (c & 7) * 8;
            cpa16(st + BH_OFF + off, Bh + g);
            cpa16(st + BL_OFF + off, Bl + g);
        }
        CP_COMMIT();
    };

    float acc[4][4][4];
#pragma unroll
    for (int i = 0; i < 4; i++)
#pragma unroll
        for (int j = 0; j < 4; j++)
#pragma unroll
            for (int q = 0; q < 4; q++) acc[i][j][q] = 0.0f;

    uint32_t ah[2][4][4], al[2][4][4], bh[2][2][4], bl[2][2][4];
    const int lrow  = lane & 15;
    const int lcolh = (lane >> 4) << 3;

    auto ldfrag = [&](uint32_t st, int kc, int buf) {
#pragma unroll
        for (int mt = 0; mt < 4; mt++) {
            int r = wm * 64 + mt * 16 + lrow;
            uint32_t off = r * 128 + (kc * 16 + lcolh) * 2;
            off ^= ((off >> 3) & 0x70);
            ldsm_x4(ah[buf][mt], st + off);
            ldsm_x4(al[buf][mt], st + AL_OFF + off);
        }
#pragma unroll
        for (int np = 0; np < 2; np++) {
            int kr = kc * 16 + lrow;
            int c  = wn * 32 + np * 16 + lcolh;
            uint32_t off = kr * 128 + c * 2;
            off ^= ((off >> 3) & 0x70);
            ldsm_x4_t(bh[buf][np], st + BH_OFF + off);
            ldsm_x4_t(bl[buf][np], st + BL_OFF + off);
        }
    };

    auto mma_chunk = [&](int buf) {
#pragma unroll
        for (int mt = 0; mt < 4; mt++)
#pragma unroll
            for (int nt = 0; nt < 4; nt++) {
                const uint32_t* bhp = &bh[buf][nt >> 1][(nt & 1) * 2];
                const uint32_t* blp = &bl[buf][nt >> 1][(nt & 1) * 2];
                mma16816(acc[mt][nt], ah[buf][mt], bhp);
                mma16816(acc[mt][nt], ah[buf][mt], blp);
                mma16816(acc[mt][nt], al[buf][mt], bhp);
            }
    };

    // decoupled per-group pipeline: 2 stages deep
    const int T   = K / BK;                // >= 4, even
    const int nit = T / 2;
    load_stage(grp);
    load_stage(grp + 2);

    for (int i = 0; i < nit; i++) {
        const int t = 2 * i + grp;
        if (i < nit - 1) CP_WAIT(1); else CP_WAIT(0);
        BAR_GRP(grp + 1);                  // group data visible
        const uint32_t st = sbase + (t & 3) * STAGE;
        ldfrag(st, 0, 0);
#pragma unroll
        for (int kc = 0; kc < 4; kc++) {
            if (kc < 3) ldfrag(st, kc + 1, (kc + 1) & 1);
            mma_chunk(kc & 1);
        }
        BAR_GRP(grp + 1);                  // group done with stage
        if (t + 4 < T) load_stage(t + 4);
    }

    // ---- cross-group reduction (stage 0 reused; CTA-sync both sides) ----
    float* red = (float*)dsm;
    __syncthreads();                       // both groups out of mainloop
    if (grp == 1) {
#pragma unroll
        for (int mt = 0; mt < 4; mt++)
#pragma unroll
            for (int nt = 0; nt < 4; nt++)
#pragma unroll
                for (int q = 0; q < 4; q++)
                    red[wg * 2048 + (mt * 16 + nt * 4 + q) * 32 + lane] = acc[mt][nt][q];
    }
    __syncthreads();
    if (grp == 1) return;
#pragma unroll
    for (int mt = 0; mt < 4; mt++)
#pragma unroll
        for (int nt = 0; nt < 4; nt++)
#pragma unroll
            for (int q = 0; q < 4; q++)
                acc[mt][nt][q] += red[wg * 2048 + (mt * 16 + nt * 4 + q) * 32 + lane];

    // ---- epilogue (group 0; full 128x64 tile) ----
    const int rr0 = brow + wm * 64 + (lane >> 2);
    const int cc0 = bcol + wn * 32 + ((lane & 3) << 1);
    float aLv = 0.f, aHv = 0.f;
    if (EPI == 3) { aLv = aLp[0]; aHv = aHp[0]; }
    const bool do_relu  = (EPI == 2) || (EPI == 4 && blockIdx.z == 0);
    const bool out_f32  = (EPI == 0) || (EPI == 4 && blockIdx.z == 1);
#pragma unroll
    for (int mt = 0; mt < 4; mt++)
#pragma unroll
        for (int nt = 0; nt < 4; nt++) {
            int row = rr0 + mt * 16;
            int col = cc0 + nt * 8;
            float2 v0 = make_float2(acc[mt][nt][0], acc[mt][nt][1]);
            float2 v1 = make_float2(acc[mt][nt][2], acc[mt][nt][3]);
            if (do_relu) {
                v0.x = fmaxf(v0.x, 0.f); v0.y = fmaxf(v0.y, 0.f);
                v1.x = fmaxf(v1.x, 0.f); v1.y = fmaxf(v1.y, 0.f);
            }
            if (out_f32) {
                *(float2*)(Cf + (size_t)row * N + col)       = v0;
                *(float2*)(Cf + (size_t)(row + 8) * N + col) = v1;
            } else if (EPI == 3) {
                float2 b = *(const float2*)&bc[col];
#pragma unroll
                for (int sr = 0; sr < 2; sr++) {
                    int rw = row + sr * 8;
                    float ds = g_dis[rw];
                    float c2 = ds * ds;
                    float2 hl = *(const float2*)&g_Hl[(size_t)rw * N + col];
                    float2 xw = *(const float2*)&g_XW[(size_t)rw * N + col];
                    float2 v  = sr ? v1 : v0;
                    float2 r;
                    r.x = aLv * (hl.x + c2 * xw.x + b.x) + aHv * v.x;
                    r.y = aLv * (hl.y + c2 * xw.y + b.y) + aHv * v.y;
                    *(float2*)(Cf + (size_t)rw * N + col) = r;
                }
            } else {
                __nv_bfloat162 h0, l0, h1, l1;
                split2(v0.x, v0.y, h0, l0);
                split2(v1.x, v1.y, h1, l1);
                *(__nv_bfloat162*)(Ch + (size_t)row * N + col)       = h0;
                *(__nv_bfloat162*)(Cl + (size_t)row * N + col)       = l0;
                *(__nv_bfloat162*)(Ch + (size_t)(row + 8) * N + col) = h1;
                *(__nv_bfloat162*)(Cl + (size_t)(row + 8) * N + col) = l1;
            }
        }
}

// ---------------- GCN branch helpers ---------------------------------------
__global__ void zero_kernel()
{
    int gid = blockIdx.x * 256 + threadIdx.x;
    if (gid < NN * DIM) g_Hl[gid] = 0.0f;
    if (gid < NN)       g_deg[gid] = 0;
}

__global__ void detect_kernel(const int* __restrict__ ei32)
{
    if (blockIdx.x == 0 && threadIdx.x == 0) {
        int is64 = 1;
        for (int i = 0; i < 256; i++)
            if (ei32[2 * i + 1] != 0) { is64 = 0; break; }
        g_is64 = is64;
    }
}

__device__ __forceinline__ int edge_at(const void* ei, int pos, int is64)
{
    return is64 ? (int)((const long long*)ei)[pos] : ((const int*)ei)[pos];
}

__global__ void deg_kernel(const void* __restrict__ ei)
{
    int e = blockIdx.x * 256 + threadIdx.x;
    if (e >= NE) return;
    int d = edge_at(ei, NE + e, g_is64);
    atomicAdd(&g_deg[d], 1);
}

__global__ void dis_kernel()
{
    int n = blockIdx.x * 256 + threadIdx.x;
    if (n < NN) g_dis[n] = rsqrtf((float)(g_deg[n] + 1));
}

__global__ void scatter_kernel(const void* __restrict__ ei)
{
    int gid = blockIdx.x * 256 + threadIdx.x;
    int e = gid >> 6;
    if (e >= NE) return;
    int q = (gid & 63) << 2;
    int is64 = g_is64;
    int s = edge_at(ei, e, is64);
    int d = edge_at(ei, NE + e, is64);
    float coef = g_dis[s] * g_dis[d];
    float4 xw = *(const float4*)&g_XW[s * DIM + q];
    float4 m = make_float4(coef * xw.x, coef * xw.y, coef * xw.z, coef * xw.w);
    atomicAdd((float4*)&g_Hl[d * DIM + q], m);
}

// ---------------- launch ----------------------------------------------------
extern "C" void kernel_launch(void* const* d_in, const int* in_sizes, int n_in,
                              void* d_out, int out_size)
{
    const float* x    = (const float*)d_in[0];
    const void*  ei   = d_in[1];
    const float* lap  = (const float*)d_in[2];
    const float* dinv = (const float*)d_in[3];
    const float* Wh   = (const float*)d_in[4];
    const float* Wc   = (const float*)d_in[5];
    const float* bc   = (const float*)d_in[6];
    const float* aL   = (const float*)d_in[7];
    const float* aH   = (const float*)d_in[8];
    float* out = (float*)d_out;

    __nv_bfloat16 *lapH, *lapL, *dH, *dL, *xH, *xL, *WhH, *WhL, *WcH, *WcL;
    __nv_bfloat16 *T0H, *T0L, *T1H, *T1L, *T2H, *T2L;
    float *XW;
    cudaGetSymbolAddress((void**)&lapH, g_lapH); cudaGetSymbolAddress((void**)&lapL, g_lapL);
    cudaGetSymbolAddress((void**)&dH,   g_dH);   cudaGetSymbolAddress((void**)&dL,   g_dL);
    cudaGetSymbolAddress((void**)&xH,   g_xH);   cudaGetSymbolAddress((void**)&xL,   g_xL);
    cudaGetSymbolAddress((void**)&WhH,  g_WhH);  cudaGetSymbolAddress((void**)&WhL,  g_WhL);
    cudaGetSymbolAddress((void**)&WcH,  g_WcH);  cudaGetSymbolAddress((void**)&WcL,  g_WcL);
    cudaGetSymbolAddress((void**)&T0H,  g_T0H);  cudaGetSymbolAddress((void**)&T0L,  g_T0L);
    cudaGetSymbolAddress((void**)&T1H,  g_T1H);  cudaGetSymbolAddress((void**)&T1L,  g_T1L);
    cudaGetSymbolAddress((void**)&T2H,  g_T2H);  cudaGetSymbolAddress((void**)&T2L,  g_T2L);
    cudaGetSymbolAddress((void**)&XW,   g_XW);

    constexpr int SMEM_BYTES = 4 * 49152;   // 192 KB dynamic smem

    static cudaStream_t side = nullptr;
    static cudaEvent_t evFork, evLap, evXW, evE3;
    if (!side) {
        cudaFuncSetAttribute(gemm_mm<1>, cudaFuncAttributeMaxDynamicSharedMemorySize, SMEM_BYTES);
        cudaFuncSetAttribute(gemm_mm<3>, cudaFuncAttributeMaxDynamicSharedMemorySize, SMEM_BYTES);
        cudaFuncSetAttribute(gemm_mm<4>, cudaFuncAttributeMaxDynamicSharedMemorySize, SMEM_BYTES);
        cudaStreamCreateWithFlags(&side, cudaStreamNonBlocking);
        cudaEventCreateWithFlags(&evFork, cudaEventDisableTiming);
        cudaEventCreateWithFlags(&evLap,  cudaEventDisableTiming);
        cudaEventCreateWithFlags(&evXW,   cudaEventDisableTiming);
        cudaEventCreateWithFlags(&evE3,   cudaEventDisableTiming);
    }

    const dim3 gridG(DIM / 64, NN / 128);      // 4 x 32 = 128 CTAs
    const dim3 gridG2(DIM / 64, NN / 128, 2);  // fused T0 + XW

    // ---- main: detect, fork ----
    detect_kernel<<<1, 32>>>((const int*)ei);
    cudaEventRecord(evFork, 0);
    cudaStreamWaitEvent(side, evFork, 0);

    // ---- main: small splits + dinv split + fused T0/XW GEMM ----
    split3<<<1152, 256>>>((const float4*)x,  (uint2*)xH,  (uint2*)xL,
                          (const float4*)Wh, (uint2*)WhH, (uint2*)WhL,
                          (const float4*)Wc, (uint2*)WcH, (uint2*)WcL);
    split_mat<<<(NN * NN / 4) / 256, 256>>>((const float4*)dinv, (uint2*)dH, (uint2*)dL, NN * NN / 4);
    gemm_mm<4><<<gridG2, 256, SMEM_BYTES>>>(xH, xL, WhH, WhL, DIM, XW, T0H, T0L,
                                            nullptr, nullptr, nullptr, WcH, WcL);
    cudaEventRecord(evXW, 0);

    // ---- side: lap split (overlaps fused GEMM), GCN prep, scatter ----
    zero_kernel<<<(NN * DIM) / 256, 256, 0, side>>>();
    deg_kernel<<<NE / 256, 256, 0, side>>>(ei);
    dis_kernel<<<NN / 256, 256, 0, side>>>();
    split_mat<<<(NN * NN / 4) / 256, 256, 0, side>>>((const float4*)lap, (uint2*)lapH, (uint2*)lapL, NN * NN / 4);
    cudaEventRecord(evLap, side);
    cudaStreamWaitEvent(side, evXW, 0);     // scatter needs XW
    scatter_kernel<<<(NE * 64) / 256, 256, 0, side>>>(ei);
    cudaEventRecord(evE3, side);

    // ---- main: high-pass chain ----
    gemm_mm<1><<<gridG, 256, SMEM_BYTES>>>(dH, dL, T0H, T0L, NN, nullptr, T1H, T1L,
                                           nullptr, nullptr, nullptr, nullptr, nullptr);
    cudaStreamWaitEvent(0, evLap, 0);       // lap split done
    gemm_mm<1><<<gridG, 256, SMEM_BYTES>>>(lapH, lapL, T1H, T1L, NN, nullptr, T2H, T2L,
                                           nullptr, nullptr, nullptr, nullptr, nullptr);
    cudaStreamWaitEvent(0, evE3, 0);        // scatter branch done
    // G3 fused combine: out = aL*(Hl + dis^2*XW + bc) + aH*(dinv @ T2)
    gemm_mm<3><<<gridG, 256, SMEM_BYTES>>>(dH, dL, T2H, T2L, NN, out, nullptr, nullptr,
                                           bc, aL, aH, nullptr, nullptr);
}